// round 2
// baseline (speedup 1.0000x reference)
#include <cuda_runtime.h>

// Problem constants
#define NLAYERS 12
#define BATCH   4
#define SEQ     1024
#define DMODEL  512
#define NHEADS  8
#define DHEAD   64
#define FDIM    2048
#define MROWS   (BATCH*SEQ)   // 4096

// ---------------------------------------------------------------------------
// Scratch (static device globals; no allocation anywhere)
// ---------------------------------------------------------------------------
__device__ float g_x[MROWS*DMODEL];
__device__ float g_q[MROWS*DMODEL];
__device__ float g_k[MROWS*DMODEL];
__device__ float g_v[MROWS*DMODEL];
__device__ float g_y[MROWS*DMODEL];
__device__ float g_t[MROWS*DMODEL];
__device__ float g_f[MROWS*FDIM];
__device__ float g_p[(long)BATCH*NHEADS*SEQ*SEQ];   // attention scores/probs (134 MB)

// ---------------------------------------------------------------------------
// 128x128x8 SGEMM, 256 threads, 8x8 microtile.
// C = A @ B (+bias)(+relu); TB => B is N-major (use B^T), CAUSAL => skip
// blocks strictly above the diagonal (contents dead; softmax rewrites tail).
// Two-level batch strides: z -> (zb, zh) with zb = z/nh, zh = z%nh.
// M,N multiples of 128; K multiple of 8.
// ---------------------------------------------------------------------------
template<bool TB, bool RELU, bool BIAS, bool CAUSAL>
__global__ __launch_bounds__(256) void gemm128_k(
    const float* __restrict__ A, const float* __restrict__ Bm,
    const float* __restrict__ bias, float* __restrict__ C,
    int K, int lda, int ldb, int ldc,
    long sAb, long sAh, long sBb, long sBh, long sCb, long sCh, int nh)
{
    const int row0 = blockIdx.y * 128;
    const int col0 = blockIdx.x * 128;
    if (CAUSAL && col0 > row0) return;

    const int zb = blockIdx.z / nh, zh = blockIdx.z % nh;
    A  += (long)zb*sAb + (long)zh*sAh;
    Bm += (long)zb*sBb + (long)zh*sBh;
    C  += (long)zb*sCb + (long)zh*sCh;

    __shared__ float As[8][132];
    __shared__ float Bs[8][132];

    const int tid = threadIdx.x;
    const int tx = tid & 15;          // 16 col-groups of 8
    const int ty = tid >> 4;          // 16 row-groups of 8

    // A (and NT-B) load indices: 128 rows x 8 k, one float4 per thread
    const int arow = tid >> 1;        // 0..127
    const int ak   = (tid & 1) << 2;  // 0 or 4
    // NN-B load indices: 8 rows x 128 cols
    const int bk = tid >> 5;          // 0..7
    const int bn = (tid & 31) << 2;   // 0..124

    float acc[8][8] = {};

    for (int k0 = 0; k0 < K; k0 += 8) {
        float4 a4 = *(const float4*)(A + (long)(row0 + arow)*lda + k0 + ak);
        As[ak+0][arow] = a4.x; As[ak+1][arow] = a4.y;
        As[ak+2][arow] = a4.z; As[ak+3][arow] = a4.w;

        if (TB) {
            float4 b4 = *(const float4*)(Bm + (long)(col0 + arow)*ldb + k0 + ak);
            Bs[ak+0][arow] = b4.x; Bs[ak+1][arow] = b4.y;
            Bs[ak+2][arow] = b4.z; Bs[ak+3][arow] = b4.w;
        } else {
            *(float4*)&Bs[bk][bn] =
                *(const float4*)(Bm + (long)(k0 + bk)*ldb + col0 + bn);
        }
        __syncthreads();

        #pragma unroll
        for (int kk = 0; kk < 8; kk++) {
            float a[8], b[8];
            *(float4*)&a[0] = *(const float4*)&As[kk][ty*8 + 0];
            *(float4*)&a[4] = *(const float4*)&As[kk][ty*8 + 4];
            *(float4*)&b[0] = *(const float4*)&Bs[kk][tx*8 + 0];
            *(float4*)&b[4] = *(const float4*)&Bs[kk][tx*8 + 4];
            #pragma unroll
            for (int i = 0; i < 8; i++)
                #pragma unroll
                for (int j = 0; j < 8; j++)
                    acc[i][j] += a[i]*b[j];
        }
        __syncthreads();
    }

    float bv[8] = {};
    if (BIAS) {
        *(float4*)&bv[0] = *(const float4*)&bias[col0 + tx*8 + 0];
        *(float4*)&bv[4] = *(const float4*)&bias[col0 + tx*8 + 4];
    }
    #pragma unroll
    for (int i = 0; i < 8; i++) {
        const long r = row0 + ty*8 + i;
        float o[8];
        #pragma unroll
        for (int j = 0; j < 8; j++) {
            o[j] = acc[i][j] + bv[j];
            if (RELU) o[j] = fmaxf(o[j], 0.f);
        }
        *(float4*)&C[r*ldc + col0 + tx*8 + 0] = *(float4*)&o[0];
        *(float4*)&C[r*ldc + col0 + tx*8 + 4] = *(float4*)&o[4];
    }
}

// ---------------------------------------------------------------------------
// 64x64x16 SGEMM (for PV, N=64). KCLAMP limits K to row0+64 (causal PV).
// ---------------------------------------------------------------------------
template<bool KCLAMP>
__global__ __launch_bounds__(256) void gemm64_k(
    const float* __restrict__ A, const float* __restrict__ Bm,
    float* __restrict__ C,
    int K, int lda, int ldb, int ldc,
    long sAb, long sAh, long sBb, long sBh, long sCb, long sCh, int nh)
{
    const int zb = blockIdx.z / nh, zh = blockIdx.z % nh;
    A  += (long)zb*sAb + (long)zh*sAh;
    Bm += (long)zb*sBb + (long)zh*sBh;
    C  += (long)zb*sCb + (long)zh*sCh;

    __shared__ float As[16][68];
    __shared__ float Bs[16][68];

    const int tid  = threadIdx.x;
    const int row0 = blockIdx.y * 64;
    const int col0 = blockIdx.x * 64;

    const int ar = tid >> 2;          // 0..63
    const int ak = (tid & 3) << 2;    // 0,4,8,12

    float acc[4][4] = {};

    const int ty4 = (tid >> 4) << 2;
    const int tx4 = (tid & 15) << 2;

    const int Kend = KCLAMP ? min(K, row0 + 64) : K;

    for (int k0 = 0; k0 < Kend; k0 += 16) {
        float4 a4 = *(const float4*)(A + (long)(row0 + ar)*lda + k0 + ak);
        As[ak+0][ar] = a4.x; As[ak+1][ar] = a4.y;
        As[ak+2][ar] = a4.z; As[ak+3][ar] = a4.w;

        const int bk = tid >> 4;          // 0..15
        const int bn = (tid & 15) << 2;   // 0..60
        *(float4*)&Bs[bk][bn] = *(const float4*)(Bm + (long)(k0 + bk)*ldb + col0 + bn);
        __syncthreads();

        #pragma unroll
        for (int kk = 0; kk < 16; kk++) {
            float4 av = *(const float4*)&As[kk][ty4];
            float4 bv = *(const float4*)&Bs[kk][tx4];
            float aa[4] = {av.x, av.y, av.z, av.w};
            float bb[4] = {bv.x, bv.y, bv.z, bv.w};
            #pragma unroll
            for (int i = 0; i < 4; i++)
                #pragma unroll
                for (int j = 0; j < 4; j++)
                    acc[i][j] += aa[i]*bb[j];
        }
        __syncthreads();
    }

    #pragma unroll
    for (int i = 0; i < 4; i++) {
        float4 o = {acc[i][0], acc[i][1], acc[i][2], acc[i][3]};
        *(float4*)&C[(long)(row0 + ty4 + i)*ldc + col0 + tx4] = o;
    }
}

// ---------------------------------------------------------------------------
// Row softmax with scale 1/sqrt(DH); causal via row length; zeros masked tail.
// ---------------------------------------------------------------------------
__global__ void softmax_k(float* __restrict__ P, int causal)
{
    const long row = blockIdx.x;
    const int  i   = (int)(row % SEQ);
    float* p = P + row * (long)SEQ;
    const int len = causal ? (i + 1) : SEQ;
    const int t = threadIdx.x;
    const float scale = 0.125f;  // 1/sqrt(64)

    __shared__ float sm[4];

    float m = -1e30f;
    for (int j = t; j < len; j += 128) m = fmaxf(m, p[j]);
    #pragma unroll
    for (int o = 16; o > 0; o >>= 1) m = fmaxf(m, __shfl_xor_sync(0xffffffffu, m, o));
    if ((t & 31) == 0) sm[t >> 5] = m;
    __syncthreads();
    m = fmaxf(fmaxf(sm[0], sm[1]), fmaxf(sm[2], sm[3]));
    __syncthreads();

    float sum = 0.f;
    for (int j = t; j < len; j += 128) {
        float e = __expf((p[j] - m) * scale);
        p[j] = e;
        sum += e;
    }
    #pragma unroll
    for (int o = 16; o > 0; o >>= 1) sum += __shfl_xor_sync(0xffffffffu, sum, o);
    if ((t & 31) == 0) sm[t >> 5] = sum;
    __syncthreads();
    sum = sm[0] + sm[1] + sm[2] + sm[3];
    const float inv = 1.f / sum;

    for (int j = t; j < len; j += 128) p[j] *= inv;
    for (int j = len + t; j < SEQ; j += 128) p[j] = 0.f;
}

// ---------------------------------------------------------------------------
// out = LayerNorm(X + Y) * g + b ; one block (128 threads) per 512-elem row.
// ---------------------------------------------------------------------------
__global__ void add_ln_k(const float* __restrict__ X, const float* __restrict__ Y,
                         const float* __restrict__ g, const float* __restrict__ b,
                         float* __restrict__ O)
{
    const long row = blockIdx.x;
    const float* x = X + row * DMODEL;
    const float* y = Y + row * DMODEL;
    float* o = O + row * DMODEL;
    const int t = threadIdx.x;

    __shared__ float sm[4];

    float v[4];
    float s = 0.f;
    #pragma unroll
    for (int i = 0; i < 4; i++) {
        int j = t + i*128;
        v[i] = x[j] + y[j];
        s += v[i];
    }
    #pragma unroll
    for (int o2 = 16; o2 > 0; o2 >>= 1) s += __shfl_xor_sync(0xffffffffu, s, o2);
    if ((t & 31) == 0) sm[t >> 5] = s;
    __syncthreads();
    const float mu = (sm[0]+sm[1]+sm[2]+sm[3]) * (1.f/DMODEL);
    __syncthreads();

    float var = 0.f;
    #pragma unroll
    for (int i = 0; i < 4; i++) { float d = v[i]-mu; var += d*d; }
    #pragma unroll
    for (int o2 = 16; o2 > 0; o2 >>= 1) var += __shfl_xor_sync(0xffffffffu, var, o2);
    if ((t & 31) == 0) sm[t >> 5] = var;
    __syncthreads();
    const float rs = rsqrtf((sm[0]+sm[1]+sm[2]+sm[3]) * (1.f/DMODEL) + 1e-5f);

    #pragma unroll
    for (int i = 0; i < 4; i++) {
        int j = t + i*128;
        o[j] = (v[i]-mu)*rs*g[j] + b[j];
    }
}

// x += pos_enc (broadcast over batch)
__global__ void addpos_k(const float* __restrict__ x, const float* __restrict__ pos,
                         float* __restrict__ o)
{
    long idx = (long)blockIdx.x * 256 + threadIdx.x;
    long sd  = idx % ((long)SEQ * DMODEL);
    o[idx] = x[idx] + pos[sd];
}

// ---------------------------------------------------------------------------
// Host-side launch helpers
// ---------------------------------------------------------------------------
// Dense: C[M,N] = A[M,K] @ B[K,N] (+bias, +relu)
static void dense_gemm(const float* A, const float* B, const float* bias, float* C,
                       int M, int N, int K, bool relu)
{
    dim3 grid(N/128, M/128, 1);
    if (relu)
        gemm128_k<false,true ,true ,false><<<grid,256>>>(A,B,bias,C,K,K,N,N,0,0,0,0,0,0,1);
    else
        gemm128_k<false,false,true ,false><<<grid,256>>>(A,B,bias,C,K,K,N,N,0,0,0,0,0,0,1);
}

// Scores: P[b,h,i,j] = Q[b,i,h,:] . K[b,j,h,:]
static void qkt_gemm(const float* Q, const float* Km, float* P, bool causal)
{
    const long SD = (long)SEQ*DMODEL;
    const long SS = (long)SEQ*SEQ;
    dim3 grid(SEQ/128, SEQ/128, BATCH*NHEADS);
    if (causal)
        gemm128_k<true,false,false,true ><<<grid,256>>>(Q,Km,nullptr,P,DHEAD,
            DMODEL,DMODEL,SEQ, SD,DHEAD, SD,DHEAD, (long)NHEADS*SS,SS, NHEADS);
    else
        gemm128_k<true,false,false,false><<<grid,256>>>(Q,Km,nullptr,P,DHEAD,
            DMODEL,DMODEL,SEQ, SD,DHEAD, SD,DHEAD, (long)NHEADS*SS,SS, NHEADS);
}

// Y[b,i,h,:] = sum_j P[b,h,i,j] V[b,j,h,:]
static void pv_gemm(const float* P, const float* V, float* Y, bool causal)
{
    const long SD = (long)SEQ*DMODEL;
    const long SS = (long)SEQ*SEQ;
    dim3 grid(DHEAD/64, SEQ/64, BATCH*NHEADS);
    if (causal)
        gemm64_k<true ><<<grid,256>>>(P,V,Y,SEQ, SEQ,DMODEL,DMODEL,
            (long)NHEADS*SS,SS, SD,DHEAD, SD,DHEAD, NHEADS);
    else
        gemm64_k<false><<<grid,256>>>(P,V,Y,SEQ, SEQ,DMODEL,DMODEL,
            (long)NHEADS*SS,SS, SD,DHEAD, SD,DHEAD, NHEADS);
}

extern "C" void kernel_launch(void* const* d_in, const int* in_sizes, int n_in,
                              void* d_out, int out_size)
{
    const float* kv   = (const float*)d_in[0];
    const float* xin  = (const float*)d_in[1];
    const float* pos  = (const float*)d_in[2];
    const float* sqW  = (const float*)d_in[3];  const float* sqb = (const float*)d_in[4];
    const float* skW  = (const float*)d_in[5];  const float* skb = (const float*)d_in[6];
    const float* svW  = (const float*)d_in[7];  const float* svb = (const float*)d_in[8];
    const float* soW  = (const float*)d_in[9];  const float* sob = (const float*)d_in[10];
    const float* cqW  = (const float*)d_in[11]; const float* cqb = (const float*)d_in[12];
    const float* ckW  = (const float*)d_in[13]; const float* ckb = (const float*)d_in[14];
    const float* cvW  = (const float*)d_in[15]; const float* cvb = (const float*)d_in[16];
    const float* coW  = (const float*)d_in[17]; const float* cob = (const float*)d_in[18];
    const float* f1W  = (const float*)d_in[19]; const float* f1b = (const float*)d_in[20];
    const float* f2W  = (const float*)d_in[21]; const float* f2b = (const float*)d_in[22];
    const float* g1   = (const float*)d_in[23]; const float* b1  = (const float*)d_in[24];
    const float* g2   = (const float*)d_in[25]; const float* b2  = (const float*)d_in[26];
    const float* g3   = (const float*)d_in[27]; const float* b3  = (const float*)d_in[28];
    float* out = (float*)d_out;

    float *px,*pq,*pk,*pv,*py,*pt,*pf,*pp;
    cudaGetSymbolAddress((void**)&px, g_x);
    cudaGetSymbolAddress((void**)&pq, g_q);
    cudaGetSymbolAddress((void**)&pk, g_k);
    cudaGetSymbolAddress((void**)&pv, g_v);
    cudaGetSymbolAddress((void**)&py, g_y);
    cudaGetSymbolAddress((void**)&pt, g_t);
    cudaGetSymbolAddress((void**)&pf, g_f);
    cudaGetSymbolAddress((void**)&pp, g_p);

    const long DD = (long)DMODEL*DMODEL;

    addpos_k<<<(MROWS*DMODEL)/256, 256>>>(xin, pos, px);

    for (int l = 0; l < NLAYERS; l++) {
        // ---- self-attention (causal) ----
        dense_gemm(px, sqW + l*DD, sqb + l*DMODEL, pq, MROWS, DMODEL, DMODEL, false);
        dense_gemm(px, skW + l*DD, skb + l*DMODEL, pk, MROWS, DMODEL, DMODEL, false);
        dense_gemm(px, svW + l*DD, svb + l*DMODEL, pv, MROWS, DMODEL, DMODEL, false);
        qkt_gemm(pq, pk, pp, true);
        softmax_k<<<BATCH*NHEADS*SEQ, 128>>>(pp, 1);
        pv_gemm(pp, pv, py, true);
        dense_gemm(py, soW + l*DD, sob + l*DMODEL, pt, MROWS, DMODEL, DMODEL, false);
        add_ln_k<<<MROWS, 128>>>(px, pt, g1 + l*DMODEL, b1 + l*DMODEL, px);

        // ---- cross-attention (no mask; K,V from kv) ----
        dense_gemm(px, cqW + l*DD, cqb + l*DMODEL, pq, MROWS, DMODEL, DMODEL, false);
        dense_gemm(kv, ckW + l*DD, ckb + l*DMODEL, pk, MROWS, DMODEL, DMODEL, false);
        dense_gemm(kv, cvW + l*DD, cvb + l*DMODEL, pv, MROWS, DMODEL, DMODEL, false);
        qkt_gemm(pq, pk, pp, false);
        softmax_k<<<BATCH*NHEADS*SEQ, 128>>>(pp, 0);
        pv_gemm(pp, pv, py, false);
        dense_gemm(py, coW + l*DD, cob + l*DMODEL, pt, MROWS, DMODEL, DMODEL, false);
        add_ln_k<<<MROWS, 128>>>(px, pt, g2 + l*DMODEL, b2 + l*DMODEL, px);

        // ---- FFN ----
        dense_gemm(px, f1W + (long)l*DMODEL*FDIM, f1b + l*FDIM, pf,
                   MROWS, FDIM, DMODEL, true);
        dense_gemm(pf, f2W + (long)l*FDIM*DMODEL, f2b + l*DMODEL, pt,
                   MROWS, DMODEL, FDIM, false);
        add_ln_k<<<MROWS, 128>>>(px, pt, g3 + l*DMODEL, b3 + l*DMODEL,
                                 (l == NLAYERS-1) ? out : px);
    }
}

// round 5
// speedup vs baseline: 1.6191x; 1.6191x over previous
#include <cuda_runtime.h>
#include <cstdint>

// Problem constants
#define NLAYERS 12
#define BATCH   4
#define SEQ     1024
#define DMODEL  512
#define NHEADS  8
#define DHEAD   64
#define FDIM    2048
#define MROWS   (BATCH*SEQ)   // 4096

// ===========================================================================
// sm_80-level PTX helpers (target-independent; no 'a'-suffix features)
// ===========================================================================
#define CP_ASYNC16(dst, src) \
    asm volatile("cp.async.cg.shared.global [%0], [%1], 16;" :: "r"(dst), "l"(src))
#define CP_COMMIT() asm volatile("cp.async.commit_group;" ::: "memory")
#define CP_WAIT0()  asm volatile("cp.async.wait_group 0;" ::: "memory")
#define CP_WAIT1()  asm volatile("cp.async.wait_group 1;" ::: "memory")

__device__ __forceinline__ void tf32_split(float x, uint32_t& hi, uint32_t& lo) {
    uint32_t h;
    asm("cvt.rna.tf32.f32 %0, %1;" : "=r"(h) : "f"(x));
    float r = x - __uint_as_float(h);
    uint32_t l;
    asm("cvt.rna.tf32.f32 %0, %1;" : "=r"(l) : "f"(r));
    hi = h; lo = l;
}

__device__ __forceinline__ void mma8(float* c, const uint32_t* a, const uint32_t* b) {
    asm volatile(
        "mma.sync.aligned.m16n8k8.row.col.f32.tf32.tf32.f32 "
        "{%0,%1,%2,%3}, {%4,%5,%6,%7}, {%8,%9}, {%0,%1,%2,%3};"
        : "+f"(c[0]), "+f"(c[1]), "+f"(c[2]), "+f"(c[3])
        : "r"(a[0]), "r"(a[1]), "r"(a[2]), "r"(a[3]), "r"(b[0]), "r"(b[1]));
}

// ===========================================================================
// Scratch (static device globals; no allocation anywhere)
// ===========================================================================
__device__ float g_x[MROWS*DMODEL];
__device__ float g_q[MROWS*DMODEL];
__device__ float g_k[MROWS*DMODEL];
__device__ float g_v[MROWS*DMODEL];
__device__ float g_y[MROWS*DMODEL];
__device__ float g_t[MROWS*DMODEL];
__device__ float g_f[MROWS*FDIM];
__device__ float g_p[(long)BATCH*NHEADS*SEQ*SEQ];   // attention scores/probs (134 MB)
__device__ float g_wt[96L*DMODEL*DMODEL + 24L*DMODEL*FDIM];  // transposed weights

// ===========================================================================
// Weight transpose: Wt[b][c][r] = W[b][r][c]
// ===========================================================================
__global__ void transpose_k(const float* __restrict__ S, float* __restrict__ D,
                            int R, int C)
{
    __shared__ float t[32][33];
    const long b = blockIdx.z;
    S += b * (long)R * C;
    D += b * (long)R * C;
    const int c0 = blockIdx.x * 32, r0 = blockIdx.y * 32;
    const int tx = threadIdx.x, ty = threadIdx.y;
    #pragma unroll
    for (int i = 0; i < 32; i += 8)
        t[ty + i][tx] = S[(long)(r0 + ty + i)*C + c0 + tx];
    __syncthreads();
    #pragma unroll
    for (int i = 0; i < 32; i += 8)
        D[(long)(c0 + ty + i)*R + r0 + tx] = t[tx][ty + i];
}

// ===========================================================================
// 3xTF32 mma.sync GEMM.
//   C[M,N] = A[M,K] @ B (+bias)(+relu)
//   TB=true : B given as Bt[N,K] row-major (i.e. col-major B)   -> SMEM [n][k]
//   TB=false: B given as B[K,N] row-major                        -> SMEM [k][n]
// Block: 256 threads, 8 warps as (8/WN) x WN grid of 64x32 warp tiles.
//   WN=4 -> 128x128 block; WN=2 -> 256x64 block.
// K-tile 16, cp.async double buffered.
// CAUSAL: skip blocks strictly above diagonal. KCLAMP: Kend = row0+BM.
// Two-level batch: z -> (zb, zh), zb=z/nh, zh=z%nh.
// Requires: M%BM==0, N%BN==0, K%16==0.
// ===========================================================================
template<int WN, bool TB, bool BIAS, bool RELU, bool CAUSAL, bool KCLAMP>
__global__ __launch_bounds__(256, 1) void gemm_mma_k(
    const float* __restrict__ A, const float* __restrict__ Bm,
    const float* __restrict__ bias, float* __restrict__ C,
    int K, int lda, int ldb, int ldc,
    long sAb, long sAh, long sBb, long sBh, long sCb, long sCh, int nh)
{
    constexpr int BM   = (8/WN)*64;
    constexpr int BN   = WN*32;
    constexpr int AS   = 20;                 // A row stride (floats): conflict-free
    constexpr int BS   = TB ? 20 : (BN + 8);
    constexpr int ABUF = BM*AS;
    constexpr int BBUF = TB ? BN*BS : 16*BS;

    const int row0 = blockIdx.y * BM;
    const int col0 = blockIdx.x * BN;
    if (CAUSAL && col0 > row0) return;

    const int zb = blockIdx.z / nh, zh = blockIdx.z % nh;
    A  += (long)zb*sAb + (long)zh*sAh;
    Bm += (long)zb*sBb + (long)zh*sBh;
    C  += (long)zb*sCb + (long)zh*sCh;

    extern __shared__ float smf[];
    float* Asm = smf;             // 2 * ABUF
    float* Bsm = smf + 2*ABUF;    // 2 * BBUF

    const int tid  = threadIdx.x;
    const int wid  = tid >> 5;
    const int lane = tid & 31;
    const int g = lane >> 2, t = lane & 3;
    const int wm = (wid / WN) * 64;
    const int wn = (wid % WN) * 32;

    const int Kend = KCLAMP ? min(K, row0 + BM) : K;
    const int ns = Kend >> 4;

    // --- async tile loaders ---
    auto loadA = [&](int s) {
        float* dst = Asm + (s & 1) * ABUF;
        #pragma unroll
        for (int it = 0; it < BM/64; it++) {
            const int idx = tid + (it << 8);
            const int r  = idx >> 2;
            const int kc = (idx & 3) << 2;
            uint32_t d = (uint32_t)__cvta_generic_to_shared(dst + r*AS + kc);
            CP_ASYNC16(d, A + (long)(row0 + r)*lda + (s << 4) + kc);
        }
    };
    auto loadB = [&](int s) {
        float* dst = Bsm + (s & 1) * BBUF;
        if (TB) {
            #pragma unroll
            for (int it = 0; it < BN/64; it++) {
                const int idx = tid + (it << 8);
                const int r  = idx >> 2;
                const int kc = (idx & 3) << 2;
                uint32_t d = (uint32_t)__cvta_generic_to_shared(dst + r*BS + kc);
                CP_ASYNC16(d, Bm + (long)(col0 + r)*ldb + (s << 4) + kc);
            }
        } else {
            #pragma unroll
            for (int it = 0; it < BN/64; it++) {
                const int idx = tid + (it << 8);
                const int kr = idx / (BN/4);
                const int nc = (idx % (BN/4)) << 2;
                uint32_t d = (uint32_t)__cvta_generic_to_shared(dst + kr*BS + nc);
                CP_ASYNC16(d, Bm + (long)((s << 4) + kr)*ldb + col0 + nc);
            }
        }
    };

    float acc[4][4][4] = {};

    loadA(0); loadB(0); CP_COMMIT();

    for (int s = 0; s < ns; s++) {
        if (s + 1 < ns) { loadA(s+1); loadB(s+1); CP_COMMIT(); CP_WAIT1(); }
        else            { CP_WAIT0(); }
        __syncthreads();

        const float* a = Asm + (s & 1) * ABUF;
        const float* b = Bsm + (s & 1) * BBUF;

        #pragma unroll
        for (int kk = 0; kk < 16; kk += 8) {
            uint32_t ahi[4][4], alo[4][4];
            #pragma unroll
            for (int i = 0; i < 4; i++) {
                const int m0 = wm + 16*i + g;
                tf32_split(a[(m0    )*AS + kk + t    ], ahi[i][0], alo[i][0]);
                tf32_split(a[(m0 + 8)*AS + kk + t    ], ahi[i][1], alo[i][1]);
                tf32_split(a[(m0    )*AS + kk + t + 4], ahi[i][2], alo[i][2]);
                tf32_split(a[(m0 + 8)*AS + kk + t + 4], ahi[i][3], alo[i][3]);
            }
            #pragma unroll
            for (int j = 0; j < 4; j++) {
                float q0, q1;
                if (TB) {
                    const int n0 = wn + 8*j + g;
                    q0 = b[n0*BS + kk + t];
                    q1 = b[n0*BS + kk + t + 4];
                } else {
                    const int n0 = wn + 8*j + g;
                    q0 = b[(kk + t    )*BS + n0];
                    q1 = b[(kk + t + 4)*BS + n0];
                }
                uint32_t bhi[2], blo[2];
                tf32_split(q0, bhi[0], blo[0]);
                tf32_split(q1, bhi[1], blo[1]);
                #pragma unroll
                for (int i = 0; i < 4; i++) {
                    mma8(acc[i][j], ahi[i], bhi);
                    mma8(acc[i][j], ahi[i], blo);
                    mma8(acc[i][j], alo[i], bhi);
                }
            }
        }
        __syncthreads();
    }

    // --- epilogue ---
    #pragma unroll
    for (int j = 0; j < 4; j++) {
        const int cb = col0 + wn + 8*j + 2*t;
        float bx = 0.f, by = 0.f;
        if (BIAS) { bx = bias[cb]; by = bias[cb + 1]; }
        #pragma unroll
        for (int i = 0; i < 4; i++) {
            const int r = row0 + wm + 16*i + g;
            float2 v0, v1;
            v0.x = acc[i][j][0] + bx; v0.y = acc[i][j][1] + by;
            v1.x = acc[i][j][2] + bx; v1.y = acc[i][j][3] + by;
            if (RELU) {
                v0.x = fmaxf(v0.x, 0.f); v0.y = fmaxf(v0.y, 0.f);
                v1.x = fmaxf(v1.x, 0.f); v1.y = fmaxf(v1.y, 0.f);
            }
            *(float2*)&C[(long)r*ldc + cb]       = v0;
            *(float2*)&C[(long)(r + 8)*ldc + cb] = v1;
        }
    }
}

// ===========================================================================
// Softmax / LayerNorm / pos-add
// ===========================================================================
__global__ void softmax_k(float* __restrict__ P, int causal)
{
    const long row = blockIdx.x;
    const int  i   = (int)(row % SEQ);
    float* p = P + row * (long)SEQ;
    const int len = causal ? (i + 1) : SEQ;
    const int t = threadIdx.x;
    const float scale = 0.125f;

    __shared__ float sm[4];
    float m = -1e30f;
    for (int j = t; j < len; j += 128) m = fmaxf(m, p[j]);
    #pragma unroll
    for (int o = 16; o > 0; o >>= 1) m = fmaxf(m, __shfl_xor_sync(0xffffffffu, m, o));
    if ((t & 31) == 0) sm[t >> 5] = m;
    __syncthreads();
    m = fmaxf(fmaxf(sm[0], sm[1]), fmaxf(sm[2], sm[3]));
    __syncthreads();
    float sum = 0.f;
    for (int j = t; j < len; j += 128) {
        float e = __expf((p[j] - m) * scale);
        p[j] = e;
        sum += e;
    }
    #pragma unroll
    for (int o = 16; o > 0; o >>= 1) sum += __shfl_xor_sync(0xffffffffu, sum, o);
    if ((t & 31) == 0) sm[t >> 5] = sum;
    __syncthreads();
    sum = sm[0] + sm[1] + sm[2] + sm[3];
    const float inv = 1.f / sum;
    for (int j = t; j < len; j += 128) p[j] *= inv;
    for (int j = len + t; j < SEQ; j += 128) p[j] = 0.f;
}

__global__ void add_ln_k(const float* __restrict__ X, const float* __restrict__ Y,
                         const float* __restrict__ g, const float* __restrict__ b,
                         float* __restrict__ O)
{
    const long row = blockIdx.x;
    const float* x = X + row * DMODEL;
    const float* y = Y + row * DMODEL;
    float* o = O + row * DMODEL;
    const int t = threadIdx.x;
    __shared__ float sm[4];

    float v[4];
    float s = 0.f;
    #pragma unroll
    for (int i = 0; i < 4; i++) {
        int j = t + i*128;
        v[i] = x[j] + y[j];
        s += v[i];
    }
    #pragma unroll
    for (int o2 = 16; o2 > 0; o2 >>= 1) s += __shfl_xor_sync(0xffffffffu, s, o2);
    if ((t & 31) == 0) sm[t >> 5] = s;
    __syncthreads();
    const float mu = (sm[0]+sm[1]+sm[2]+sm[3]) * (1.f/DMODEL);
    __syncthreads();
    float var = 0.f;
    #pragma unroll
    for (int i = 0; i < 4; i++) { float d = v[i]-mu; var += d*d; }
    #pragma unroll
    for (int o2 = 16; o2 > 0; o2 >>= 1) var += __shfl_xor_sync(0xffffffffu, var, o2);
    if ((t & 31) == 0) sm[t >> 5] = var;
    __syncthreads();
    const float rs = rsqrtf((sm[0]+sm[1]+sm[2]+sm[3]) * (1.f/DMODEL) + 1e-5f);
    #pragma unroll
    for (int i = 0; i < 4; i++) {
        int j = t + i*128;
        o[j] = (v[i]-mu)*rs*g[j] + b[j];
    }
}

__global__ void addpos_k(const float* __restrict__ x, const float* __restrict__ pos,
                         float* __restrict__ o)
{
    long idx = (long)blockIdx.x * 256 + threadIdx.x;
    long sd  = idx % ((long)SEQ * DMODEL);
    o[idx] = x[idx] + pos[sd];
}

// ===========================================================================
// Host-side launch helpers
// ===========================================================================
static const int SMEM_D = 2*(128*20 + 128*20)*4;       // dense / QK^T (WN=4, TB)
static const int SMEM_P = 2*(256*20 + 16*72)*4;        // PV (WN=2, non-TB)

static void dense_gemm(const float* A, const float* Bt, const float* bias, float* C,
                       int M, int N, int K, bool relu)
{
    dim3 grid(N/128, M/128, 1);
    if (relu)
        gemm_mma_k<4,true,true,true ,false,false><<<grid,256,SMEM_D>>>(
            A,Bt,bias,C,K, K,K,N, 0,0,0,0,0,0, 1);
    else
        gemm_mma_k<4,true,true,false,false,false><<<grid,256,SMEM_D>>>(
            A,Bt,bias,C,K, K,K,N, 0,0,0,0,0,0, 1);
}

static void qkt_gemm(const float* Q, const float* Km, float* P, bool causal)
{
    const long SD = (long)SEQ*DMODEL;
    const long SS = (long)SEQ*SEQ;
    dim3 grid(SEQ/128, SEQ/128, BATCH*NHEADS);
    if (causal)
        gemm_mma_k<4,true,false,false,true ,false><<<grid,256,SMEM_D>>>(
            Q,Km,nullptr,P,DHEAD, DMODEL,DMODEL,SEQ,
            SD,DHEAD, SD,DHEAD, (long)NHEADS*SS,SS, NHEADS);
    else
        gemm_mma_k<4,true,false,false,false,false><<<grid,256,SMEM_D>>>(
            Q,Km,nullptr,P,DHEAD, DMODEL,DMODEL,SEQ,
            SD,DHEAD, SD,DHEAD, (long)NHEADS*SS,SS, NHEADS);
}

static void pv_gemm(const float* P, const float* V, float* Y, bool causal)
{
    const long SD = (long)SEQ*DMODEL;
    const long SS = (long)SEQ*SEQ;
    dim3 grid(DHEAD/64, SEQ/256, BATCH*NHEADS);
    if (causal)
        gemm_mma_k<2,false,false,false,false,true ><<<grid,256,SMEM_P>>>(
            P,V,nullptr,Y,SEQ, SEQ,DMODEL,DMODEL,
            (long)NHEADS*SS,SS, SD,DHEAD, SD,DHEAD, NHEADS);
    else
        gemm_mma_k<2,false,false,false,false,false><<<grid,256,SMEM_P>>>(
            P,V,nullptr,Y,SEQ, SEQ,DMODEL,DMODEL,
            (long)NHEADS*SS,SS, SD,DHEAD, SD,DHEAD, NHEADS);
}

extern "C" void kernel_launch(void* const* d_in, const int* in_sizes, int n_in,
                              void* d_out, int out_size)
{
    const float* kv   = (const float*)d_in[0];
    const float* xin  = (const float*)d_in[1];
    const float* pos  = (const float*)d_in[2];
    const float* sqW  = (const float*)d_in[3];  const float* sqb = (const float*)d_in[4];
    const float* skW  = (const float*)d_in[5];  const float* skb = (const float*)d_in[6];
    const float* svW  = (const float*)d_in[7];  const float* svb = (const float*)d_in[8];
    const float* soW  = (const float*)d_in[9];  const float* sob = (const float*)d_in[10];
    const float* cqW  = (const float*)d_in[11]; const float* cqb = (const float*)d_in[12];
    const float* ckW  = (const float*)d_in[13]; const float* ckb = (const float*)d_in[14];
    const float* cvW  = (const float*)d_in[15]; const float* cvb = (const float*)d_in[16];
    const float* coW  = (const float*)d_in[17]; const float* cob = (const float*)d_in[18];
    const float* f1W  = (const float*)d_in[19]; const float* f1b = (const float*)d_in[20];
    const float* f2W  = (const float*)d_in[21]; const float* f2b = (const float*)d_in[22];
    const float* g1   = (const float*)d_in[23]; const float* b1  = (const float*)d_in[24];
    const float* g2   = (const float*)d_in[25]; const float* b2  = (const float*)d_in[26];
    const float* g3   = (const float*)d_in[27]; const float* b3  = (const float*)d_in[28];
    float* out = (float*)d_out;

    // Allow >48KB dynamic smem for all used instantiations
    cudaFuncSetAttribute(gemm_mma_k<4,true,true ,false,false,false>, cudaFuncAttributeMaxDynamicSharedMemorySize, SMEM_D);
    cudaFuncSetAttribute(gemm_mma_k<4,true,true ,true ,false,false>, cudaFuncAttributeMaxDynamicSharedMemorySize, SMEM_D);
    cudaFuncSetAttribute(gemm_mma_k<4,true,false,false,true ,false>, cudaFuncAttributeMaxDynamicSharedMemorySize, SMEM_D);
    cudaFuncSetAttribute(gemm_mma_k<4,true,false,false,false,false>, cudaFuncAttributeMaxDynamicSharedMemorySize, SMEM_D);
    cudaFuncSetAttribute(gemm_mma_k<2,false,false,false,false,true >, cudaFuncAttributeMaxDynamicSharedMemorySize, SMEM_P);
    cudaFuncSetAttribute(gemm_mma_k<2,false,false,false,false,false>, cudaFuncAttributeMaxDynamicSharedMemorySize, SMEM_P);

    float *px,*pq,*pk,*pv,*py,*pt,*pf,*pp,*pwt;
    cudaGetSymbolAddress((void**)&px, g_x);
    cudaGetSymbolAddress((void**)&pq, g_q);
    cudaGetSymbolAddress((void**)&pk, g_k);
    cudaGetSymbolAddress((void**)&pv, g_v);
    cudaGetSymbolAddress((void**)&py, g_y);
    cudaGetSymbolAddress((void**)&pt, g_t);
    cudaGetSymbolAddress((void**)&pf, g_f);
    cudaGetSymbolAddress((void**)&pp, g_p);
    cudaGetSymbolAddress((void**)&pwt, g_wt);

    const long DD = (long)DMODEL*DMODEL;
    const long DF = (long)DMODEL*FDIM;

    float* sqT = pwt + 0*12*DD;  float* skT = pwt + 12*DD;
    float* svT = pwt + 24*DD;    float* soT = pwt + 36*DD;
    float* cqT = pwt + 48*DD;    float* ckT = pwt + 60*DD;
    float* cvT = pwt + 72*DD;    float* coT = pwt + 84*DD;
    float* f1T = pwt + 96*DD;            // [L][FDIM][DMODEL]
    float* f2T = f1T + 12*DF;            // [L][DMODEL][FDIM]

    {
        dim3 blk(32, 8);
        transpose_k<<<dim3(16,16,NLAYERS), blk>>>(sqW, sqT, DMODEL, DMODEL);
        transpose_k<<<dim3(16,16,NLAYERS), blk>>>(skW, skT, DMODEL, DMODEL);
        transpose_k<<<dim3(16,16,NLAYERS), blk>>>(svW, svT, DMODEL, DMODEL);
        transpose_k<<<dim3(16,16,NLAYERS), blk>>>(soW, soT, DMODEL, DMODEL);
        transpose_k<<<dim3(16,16,NLAYERS), blk>>>(cqW, cqT, DMODEL, DMODEL);
        transpose_k<<<dim3(16,16,NLAYERS), blk>>>(ckW, ckT, DMODEL, DMODEL);
        transpose_k<<<dim3(16,16,NLAYERS), blk>>>(cvW, cvT, DMODEL, DMODEL);
        transpose_k<<<dim3(16,16,NLAYERS), blk>>>(coW, coT, DMODEL, DMODEL);
        transpose_k<<<dim3(64,16,NLAYERS), blk>>>(f1W, f1T, DMODEL, FDIM);
        transpose_k<<<dim3(16,64,NLAYERS), blk>>>(f2W, f2T, FDIM, DMODEL);
    }

    addpos_k<<<(MROWS*DMODEL)/256, 256>>>(xin, pos, px);

    for (int l = 0; l < NLAYERS; l++) {
        // ---- self-attention (causal) ----
        dense_gemm(px, sqT + l*DD, sqb + l*DMODEL, pq, MROWS, DMODEL, DMODEL, false);
        dense_gemm(px, skT + l*DD, skb + l*DMODEL, pk, MROWS, DMODEL, DMODEL, false);
        dense_gemm(px, svT + l*DD, svb + l*DMODEL, pv, MROWS, DMODEL, DMODEL, false);
        qkt_gemm(pq, pk, pp, true);
        softmax_k<<<BATCH*NHEADS*SEQ, 128>>>(pp, 1);
        pv_gemm(pp, pv, py, true);
        dense_gemm(py, soT + l*DD, sob + l*DMODEL, pt, MROWS, DMODEL, DMODEL, false);
        add_ln_k<<<MROWS, 128>>>(px, pt, g1 + l*DMODEL, b1 + l*DMODEL, px);

        // ---- cross-attention ----
        dense_gemm(px, cqT + l*DD, cqb + l*DMODEL, pq, MROWS, DMODEL, DMODEL, false);
        dense_gemm(kv, ckT + l*DD, ckb + l*DMODEL, pk, MROWS, DMODEL, DMODEL, false);
        dense_gemm(kv, cvT + l*DD, cvb + l*DMODEL, pv, MROWS, DMODEL, DMODEL, false);
        qkt_gemm(pq, pk, pp, false);
        softmax_k<<<BATCH*NHEADS*SEQ, 128>>>(pp, 0);
        pv_gemm(pp, pv, py, false);
        dense_gemm(py, coT + l*DD, cob + l*DMODEL, pt, MROWS, DMODEL, DMODEL, false);
        add_ln_k<<<MROWS, 128>>>(px, pt, g2 + l*DMODEL, b2 + l*DMODEL, px);

        // ---- FFN ----
        dense_gemm(px, f1T + l*DF, f1b + l*FDIM, pf, MROWS, FDIM, DMODEL, true);
        dense_gemm(pf, f2T + l*DF, f2b + l*DMODEL, pt, MROWS, DMODEL, FDIM, false);
        add_ln_k<<<MROWS, 128>>>(px, pt, g3 + l*DMODEL, b3 + l*DMODEL,
                                 (l == NLAYERS-1) ? out : px);
    }
}

// round 6
// speedup vs baseline: 1.7758x; 1.0968x over previous
#include <cuda_runtime.h>
#include <cstdint>

// Problem constants
#define NLAYERS 12
#define BATCH   4
#define SEQ     1024
#define DMODEL  512
#define NHEADS  8
#define DHEAD   64
#define FDIM    2048
#define MROWS   (BATCH*SEQ)   // 4096

// ===========================================================================
// sm_80-level PTX helpers
// ===========================================================================
#define CP_ASYNC16(dst, src) \
    asm volatile("cp.async.cg.shared.global [%0], [%1], 16;" :: "r"(dst), "l"(src))
#define CP_COMMIT() asm volatile("cp.async.commit_group;" ::: "memory")
#define CP_WAIT0()  asm volatile("cp.async.wait_group 0;" ::: "memory")
#define CP_WAIT1()  asm volatile("cp.async.wait_group 1;" ::: "memory")

__device__ __forceinline__ void tf32_split(float x, uint32_t& hi, uint32_t& lo) {
    uint32_t h;
    asm("cvt.rna.tf32.f32 %0, %1;" : "=r"(h) : "f"(x));
    float r = x - __uint_as_float(h);
    uint32_t l;
    asm("cvt.rna.tf32.f32 %0, %1;" : "=r"(l) : "f"(r));
    hi = h; lo = l;
}

// Split two fp32 (k-adjacent pair) into packed bf16x2 hi and lo parts.
// Lower 16 bits hold x0 (even k), upper hold x1 (odd k).
__device__ __forceinline__ void bf16_split2(float x0, float x1,
                                            uint32_t& hi, uint32_t& lo) {
    uint32_t h;
    asm("cvt.rn.bf16x2.f32 %0, %1, %2;" : "=r"(h) : "f"(x1), "f"(x0));
    float h0 = __uint_as_float(h << 16);
    float h1 = __uint_as_float(h & 0xffff0000u);
    float r0 = x0 - h0, r1 = x1 - h1;
    uint32_t l;
    asm("cvt.rn.bf16x2.f32 %0, %1, %2;" : "=r"(l) : "f"(r1), "f"(r0));
    hi = h; lo = l;
}

__device__ __forceinline__ void mma8(float* c, const uint32_t* a, const uint32_t* b) {
    asm volatile(
        "mma.sync.aligned.m16n8k8.row.col.f32.tf32.tf32.f32 "
        "{%0,%1,%2,%3}, {%4,%5,%6,%7}, {%8,%9}, {%0,%1,%2,%3};"
        : "+f"(c[0]), "+f"(c[1]), "+f"(c[2]), "+f"(c[3])
        : "r"(a[0]), "r"(a[1]), "r"(a[2]), "r"(a[3]), "r"(b[0]), "r"(b[1]));
}

__device__ __forceinline__ void mma16(float* c, const uint32_t* a, const uint32_t* b) {
    asm volatile(
        "mma.sync.aligned.m16n8k16.row.col.f32.bf16.bf16.f32 "
        "{%0,%1,%2,%3}, {%4,%5,%6,%7}, {%8,%9}, {%0,%1,%2,%3};"
        : "+f"(c[0]), "+f"(c[1]), "+f"(c[2]), "+f"(c[3])
        : "r"(a[0]), "r"(a[1]), "r"(a[2]), "r"(a[3]), "r"(b[0]), "r"(b[1]));
}

// ===========================================================================
// Scratch (static device globals; no allocation anywhere)
// ===========================================================================
__device__ float g_x[MROWS*DMODEL];
__device__ float g_qkv[3L*MROWS*DMODEL];     // q, k, v slabs
__device__ float g_y[MROWS*DMODEL];
__device__ float g_t[MROWS*DMODEL];
__device__ float g_f[MROWS*FDIM];
__device__ float g_p[(long)BATCH*NHEADS*SEQ*SEQ];   // attention scores/probs
__device__ float g_wt[96L*DMODEL*DMODEL + 24L*DMODEL*FDIM];  // transposed weights
__device__ float g_bias[4L*NLAYERS*DMODEL];  // packed biases: sq, sk, ck, cv

// ===========================================================================
// Weight transpose: Wt[b][c][r] = W[b][r][c]
// ===========================================================================
__global__ void transpose_k(const float* __restrict__ S, float* __restrict__ D,
                            int R, int C)
{
    __shared__ float t[32][33];
    const long b = blockIdx.z;
    S += b * (long)R * C;
    D += b * (long)R * C;
    const int c0 = blockIdx.x * 32, r0 = blockIdx.y * 32;
    const int tx = threadIdx.x, ty = threadIdx.y;
    #pragma unroll
    for (int i = 0; i < 32; i += 8)
        t[ty + i][tx] = S[(long)(r0 + ty + i)*C + c0 + tx];
    __syncthreads();
    #pragma unroll
    for (int i = 0; i < 32; i += 8)
        D[(long)(c0 + ty + i)*R + r0 + tx] = t[tx][ty + i];
}

__global__ void packbias_k(const float* __restrict__ a0, const float* __restrict__ a1,
                           const float* __restrict__ a2, const float* __restrict__ a3,
                           float* __restrict__ dst)
{
    const int i = blockIdx.x*256 + threadIdx.x;  // 4 * 12*512 = 24576
    const int f = i / (NLAYERS*DMODEL), r = i % (NLAYERS*DMODEL);
    const float* s = (f == 0) ? a0 : (f == 1) ? a1 : (f == 2) ? a2 : a3;
    dst[i] = s[r];
}

// ===========================================================================
// mma.sync GEMM.  PREC 0 = 3xTF32 (21-bit), PREC 1 = 2xbf16 (16-bit).
//   C[M,N] = A[M,K] @ B (+bias)(+relu)
//   TB=true : B given as Bt[N,K] row-major -> SMEM [n][k]
//   TB=false: B given as B[K,N] row-major  -> SMEM [k][n]
// 256 threads, 8 warps as (8/WN) x WN grid of 64x32 warp tiles.
//   WN=4 -> 128x128 block; WN=2 -> 256x64 block.
// K-tile 16, cp.async double buffered. CAUSAL: skip blocks above diag.
// KCLAMP: Kend = row0+BM. Batch: z -> (zb, zh), zb=z/nh, zh=z%nh.
// sbz: bias z-stride (elements) applied with zb.
// ===========================================================================
template<int PREC, int WN, bool TB, bool BIAS, bool RELU, bool CAUSAL, bool KCLAMP>
__global__ __launch_bounds__(256, 1) void gemm_mma_k(
    const float* __restrict__ A, const float* __restrict__ Bm,
    const float* __restrict__ bias, float* __restrict__ C,
    int K, int lda, int ldb, int ldc,
    long sAb, long sAh, long sBb, long sBh, long sCb, long sCh, int nh, long sbz)
{
    constexpr int BM   = (8/WN)*64;
    constexpr int BN   = WN*32;
    constexpr int AS   = 20;
    constexpr int BS   = TB ? 20 : (BN + 8);
    constexpr int ABUF = BM*AS;
    constexpr int BBUF = TB ? BN*BS : 16*BS;

    const int row0 = blockIdx.y * BM;
    const int col0 = blockIdx.x * BN;
    if (CAUSAL && col0 > row0) return;

    const int zb = blockIdx.z / nh, zh = blockIdx.z % nh;
    A  += (long)zb*sAb + (long)zh*sAh;
    Bm += (long)zb*sBb + (long)zh*sBh;
    C  += (long)zb*sCb + (long)zh*sCh;
    if (BIAS) bias += (long)zb*sbz;

    extern __shared__ float smf[];
    float* Asm = smf;
    float* Bsm = smf + 2*ABUF;

    const int tid  = threadIdx.x;
    const int wid  = tid >> 5;
    const int lane = tid & 31;
    const int g = lane >> 2, t = lane & 3;
    const int wm = (wid / WN) * 64;
    const int wn = (wid % WN) * 32;

    const int Kend = KCLAMP ? min(K, row0 + BM) : K;
    const int ns = Kend >> 4;

    auto loadA = [&](int s) {
        float* dst = Asm + (s & 1) * ABUF;
        #pragma unroll
        for (int it = 0; it < BM/64; it++) {
            const int idx = tid + (it << 8);
            const int r  = idx >> 2;
            const int kc = (idx & 3) << 2;
            uint32_t d = (uint32_t)__cvta_generic_to_shared(dst + r*AS + kc);
            CP_ASYNC16(d, A + (long)(row0 + r)*lda + (s << 4) + kc);
        }
    };
    auto loadB = [&](int s) {
        float* dst = Bsm + (s & 1) * BBUF;
        if (TB) {
            #pragma unroll
            for (int it = 0; it < BN/64; it++) {
                const int idx = tid + (it << 8);
                const int r  = idx >> 2;
                const int kc = (idx & 3) << 2;
                uint32_t d = (uint32_t)__cvta_generic_to_shared(dst + r*BS + kc);
                CP_ASYNC16(d, Bm + (long)(col0 + r)*ldb + (s << 4) + kc);
            }
        } else {
            #pragma unroll
            for (int it = 0; it < BN/64; it++) {
                const int idx = tid + (it << 8);
                const int kr = idx / (BN/4);
                const int nc = (idx % (BN/4)) << 2;
                uint32_t d = (uint32_t)__cvta_generic_to_shared(dst + kr*BS + nc);
                CP_ASYNC16(d, Bm + (long)((s << 4) + kr)*ldb + col0 + nc);
            }
        }
    };

    float acc[4][4][4] = {};

    loadA(0); loadB(0); CP_COMMIT();

    for (int s = 0; s < ns; s++) {
        if (s + 1 < ns) { loadA(s+1); loadB(s+1); CP_COMMIT(); CP_WAIT1(); }
        else            { CP_WAIT0(); }
        __syncthreads();

        const float* a = Asm + (s & 1) * ABUF;
        const float* b = Bsm + (s & 1) * BBUF;

        if (PREC == 0) {
            #pragma unroll
            for (int kk = 0; kk < 16; kk += 8) {
                uint32_t ahi[4][4], alo[4][4];
                #pragma unroll
                for (int i = 0; i < 4; i++) {
                    const int m0 = wm + 16*i + g;
                    tf32_split(a[(m0    )*AS + kk + t    ], ahi[i][0], alo[i][0]);
                    tf32_split(a[(m0 + 8)*AS + kk + t    ], ahi[i][1], alo[i][1]);
                    tf32_split(a[(m0    )*AS + kk + t + 4], ahi[i][2], alo[i][2]);
                    tf32_split(a[(m0 + 8)*AS + kk + t + 4], ahi[i][3], alo[i][3]);
                }
                #pragma unroll
                for (int j = 0; j < 4; j++) {
                    const int n0 = wn + 8*j + g;
                    float q0, q1;
                    if (TB) { q0 = b[n0*BS + kk + t]; q1 = b[n0*BS + kk + t + 4]; }
                    else    { q0 = b[(kk + t)*BS + n0]; q1 = b[(kk + t + 4)*BS + n0]; }
                    uint32_t bhi[2], blo[2];
                    tf32_split(q0, bhi[0], blo[0]);
                    tf32_split(q1, bhi[1], blo[1]);
                    #pragma unroll
                    for (int i = 0; i < 4; i++) {
                        mma8(acc[i][j], ahi[i], bhi);
                        mma8(acc[i][j], ahi[i], blo);
                        mma8(acc[i][j], alo[i], bhi);
                    }
                }
            }
        } else {
            // 2xbf16: one m16n8k16 step covers the 16-K tile
            uint32_t ahi[4][4], alo[4][4];
            #pragma unroll
            for (int i = 0; i < 4; i++) {
                const int m0 = wm + 16*i + g;
                #pragma unroll
                for (int rr = 0; rr < 4; rr++) {
                    const int r  = m0 + ((rr & 1) << 3);
                    const int kc = 2*t + ((rr >> 1) << 3);
                    float2 x = *(const float2*)&a[r*AS + kc];
                    bf16_split2(x.x, x.y, ahi[i][rr], alo[i][rr]);
                }
            }
            #pragma unroll
            for (int j = 0; j < 4; j++) {
                const int n0 = wn + 8*j + g;
                uint32_t bhi[2], blo[2];
                #pragma unroll
                for (int rr = 0; rr < 2; rr++) {
                    const int kc = 2*t + (rr << 3);
                    float x0, x1;
                    if (TB) {
                        float2 x = *(const float2*)&b[n0*BS + kc];
                        x0 = x.x; x1 = x.y;
                    } else {
                        x0 = b[(kc    )*BS + n0];
                        x1 = b[(kc + 1)*BS + n0];
                    }
                    bf16_split2(x0, x1, bhi[rr], blo[rr]);
                }
                #pragma unroll
                for (int i = 0; i < 4; i++) {
                    mma16(acc[i][j], ahi[i], bhi);
                    mma16(acc[i][j], ahi[i], blo);
                    mma16(acc[i][j], alo[i], bhi);
                }
            }
        }
        __syncthreads();
    }

    // --- epilogue ---
    #pragma unroll
    for (int j = 0; j < 4; j++) {
        const int cb = col0 + wn + 8*j + 2*t;
        float bx = 0.f, by = 0.f;
        if (BIAS) { bx = bias[cb]; by = bias[cb + 1]; }
        #pragma unroll
        for (int i = 0; i < 4; i++) {
            const int r = row0 + wm + 16*i + g;
            float2 v0, v1;
            v0.x = acc[i][j][0] + bx; v0.y = acc[i][j][1] + by;
            v1.x = acc[i][j][2] + bx; v1.y = acc[i][j][3] + by;
            if (RELU) {
                v0.x = fmaxf(v0.x, 0.f); v0.y = fmaxf(v0.y, 0.f);
                v1.x = fmaxf(v1.x, 0.f); v1.y = fmaxf(v1.y, 0.f);
            }
            *(float2*)&C[(long)r*ldc + cb]       = v0;
            *(float2*)&C[(long)(r + 8)*ldc + cb] = v1;
        }
    }
}

// ===========================================================================
// Single-pass softmax: 256 threads/row, 1 float4/thread. Scale folded in.
// Causal: zero-fills tail up to the PV block boundary (ceil-256).
// ===========================================================================
__global__ void softmax_k(float* __restrict__ P, int causal)
{
    const long row = blockIdx.x;
    const int  i   = (int)(row % SEQ);
    float* p = P + row * (long)SEQ;
    const int len  = causal ? (i + 1) : SEQ;
    const int kend = causal ? (((i >> 8) + 1) << 8) : SEQ;
    const int t = threadIdx.x;
    const int c0 = t << 2;
    const float scale = 0.125f;  // 1/sqrt(64)

    __shared__ float sm[8];

    float v0 = -1e30f, v1 = -1e30f, v2 = -1e30f, v3 = -1e30f;
    if (c0 < len) {
        float4 x = *(const float4*)&p[c0];
        v0 = x.x;
        v1 = (c0 + 1 < len) ? x.y : -1e30f;
        v2 = (c0 + 2 < len) ? x.z : -1e30f;
        v3 = (c0 + 3 < len) ? x.w : -1e30f;
    }
    float m = fmaxf(fmaxf(v0, v1), fmaxf(v2, v3));
    #pragma unroll
    for (int o = 16; o > 0; o >>= 1) m = fmaxf(m, __shfl_xor_sync(0xffffffffu, m, o));
    if ((t & 31) == 0) sm[t >> 5] = m;
    __syncthreads();
    m = sm[0];
    #pragma unroll
    for (int w = 1; w < 8; w++) m = fmaxf(m, sm[w]);
    __syncthreads();

    float e0 = (c0     < len) ? __expf((v0 - m) * scale) : 0.f;
    float e1 = (c0 + 1 < len) ? __expf((v1 - m) * scale) : 0.f;
    float e2 = (c0 + 2 < len) ? __expf((v2 - m) * scale) : 0.f;
    float e3 = (c0 + 3 < len) ? __expf((v3 - m) * scale) : 0.f;
    float sum = e0 + e1 + e2 + e3;
    #pragma unroll
    for (int o = 16; o > 0; o >>= 1) sum += __shfl_xor_sync(0xffffffffu, sum, o);
    if ((t & 31) == 0) sm[t >> 5] = sum;
    __syncthreads();
    sum = sm[0] + sm[1] + sm[2] + sm[3] + sm[4] + sm[5] + sm[6] + sm[7];
    const float inv = 1.f / sum;

    if (c0 < kend) {
        float4 o = {e0*inv, e1*inv, e2*inv, e3*inv};
        *(float4*)&p[c0] = o;
    }
}

// ===========================================================================
// out = LayerNorm(X + Y) * g + b
// ===========================================================================
__global__ void add_ln_k(const float* __restrict__ X, const float* __restrict__ Y,
                         const float* __restrict__ g, const float* __restrict__ b,
                         float* __restrict__ O)
{
    const long row = blockIdx.x;
    const float* x = X + row * DMODEL;
    const float* y = Y + row * DMODEL;
    float* o = O + row * DMODEL;
    const int t = threadIdx.x;
    __shared__ float sm[4];

    float v[4];
    float s = 0.f;
    #pragma unroll
    for (int i = 0; i < 4; i++) {
        int j = t + i*128;
        v[i] = x[j] + y[j];
        s += v[i];
    }
    #pragma unroll
    for (int o2 = 16; o2 > 0; o2 >>= 1) s += __shfl_xor_sync(0xffffffffu, s, o2);
    if ((t & 31) == 0) sm[t >> 5] = s;
    __syncthreads();
    const float mu = (sm[0]+sm[1]+sm[2]+sm[3]) * (1.f/DMODEL);
    __syncthreads();
    float var = 0.f;
    #pragma unroll
    for (int i = 0; i < 4; i++) { float d = v[i]-mu; var += d*d; }
    #pragma unroll
    for (int o2 = 16; o2 > 0; o2 >>= 1) var += __shfl_xor_sync(0xffffffffu, var, o2);
    if ((t & 31) == 0) sm[t >> 5] = var;
    __syncthreads();
    const float rs = rsqrtf((sm[0]+sm[1]+sm[2]+sm[3]) * (1.f/DMODEL) + 1e-5f);
    #pragma unroll
    for (int i = 0; i < 4; i++) {
        int j = t + i*128;
        o[j] = (v[i]-mu)*rs*g[j] + b[j];
    }
}

__global__ void addpos_k(const float* __restrict__ x, const float* __restrict__ pos,
                         float* __restrict__ o)
{
    long idx = (long)blockIdx.x * 256 + threadIdx.x;
    long sd  = idx % ((long)SEQ * DMODEL);
    o[idx] = x[idx] + pos[sd];
}

// ===========================================================================
// Host-side launch helpers
// ===========================================================================
static const int SMEM_D = 2*(128*20 + 128*20)*4;       // WN=4, TB
static const int SMEM_P = 2*(256*20 + 16*72)*4;        // WN=2, non-TB

// tf32 dense, batched over z (weights stride sBb, out stride sCb, bias stride sbz)
static void dense32(const float* A, const float* Bt, const float* bias, float* C,
                    int M, int N, int K, long sBb, long sCb, long sbz, int nz)
{
    dim3 grid(N/128, M/128, nz);
    gemm_mma_k<0,4,true,true,false,false,false><<<grid,256,SMEM_D>>>(
        A,Bt,bias,C,K, K,K,N, 0,0, sBb,0, sCb,0, 1, sbz);
}
// bf16 dense
static void dense16(const float* A, const float* Bt, const float* bias, float* C,
                    int M, int N, int K, bool relu)
{
    dim3 grid(N/128, M/128, 1);
    if (relu)
        gemm_mma_k<1,4,true,true,true ,false,false><<<grid,256,SMEM_D>>>(
            A,Bt,bias,C,K, K,K,N, 0,0,0,0,0,0, 1, 0);
    else
        gemm_mma_k<1,4,true,true,false,false,false><<<grid,256,SMEM_D>>>(
            A,Bt,bias,C,K, K,K,N, 0,0,0,0,0,0, 1, 0);
}

static void qkt_gemm(const float* Q, const float* Km, float* P, bool causal)
{
    const long SD = (long)SEQ*DMODEL;
    const long SS = (long)SEQ*SEQ;
    dim3 grid(SEQ/128, SEQ/128, BATCH*NHEADS);
    if (causal)
        gemm_mma_k<0,4,true,false,false,true ,false><<<grid,256,SMEM_D>>>(
            Q,Km,nullptr,P,DHEAD, DMODEL,DMODEL,SEQ,
            SD,DHEAD, SD,DHEAD, (long)NHEADS*SS,SS, NHEADS, 0);
    else
        gemm_mma_k<0,4,true,false,false,false,false><<<grid,256,SMEM_D>>>(
            Q,Km,nullptr,P,DHEAD, DMODEL,DMODEL,SEQ,
            SD,DHEAD, SD,DHEAD, (long)NHEADS*SS,SS, NHEADS, 0);
}

static void pv_gemm(const float* P, const float* V, float* Y, bool causal)
{
    const long SD = (long)SEQ*DMODEL;
    const long SS = (long)SEQ*SEQ;
    dim3 grid(DHEAD/64, SEQ/256, BATCH*NHEADS);
    if (causal)
        gemm_mma_k<1,2,false,false,false,false,true ><<<grid,256,SMEM_P>>>(
            P,V,nullptr,Y,SEQ, SEQ,DMODEL,DMODEL,
            (long)NHEADS*SS,SS, SD,DHEAD, SD,DHEAD, NHEADS, 0);
    else
        gemm_mma_k<1,2,false,false,false,false,false><<<grid,256,SMEM_P>>>(
            P,V,nullptr,Y,SEQ, SEQ,DMODEL,DMODEL,
            (long)NHEADS*SS,SS, SD,DHEAD, SD,DHEAD, NHEADS, 0);
}

extern "C" void kernel_launch(void* const* d_in, const int* in_sizes, int n_in,
                              void* d_out, int out_size)
{
    const float* kv   = (const float*)d_in[0];
    const float* xin  = (const float*)d_in[1];
    const float* pos  = (const float*)d_in[2];
    const float* sqW  = (const float*)d_in[3];  const float* sqb = (const float*)d_in[4];
    const float* skW  = (const float*)d_in[5];  const float* skb = (const float*)d_in[6];
    const float* svW  = (const float*)d_in[7];  const float* svb = (const float*)d_in[8];
    const float* soW  = (const float*)d_in[9];  const float* sob = (const float*)d_in[10];
    const float* cqW  = (const float*)d_in[11]; const float* cqb = (const float*)d_in[12];
    const float* ckW  = (const float*)d_in[13]; const float* ckb = (const float*)d_in[14];
    const float* cvW  = (const float*)d_in[15]; const float* cvb = (const float*)d_in[16];
    const float* coW  = (const float*)d_in[17]; const float* cob = (const float*)d_in[18];
    const float* f1W  = (const float*)d_in[19]; const float* f1b = (const float*)d_in[20];
    const float* f2W  = (const float*)d_in[21]; const float* f2b = (const float*)d_in[22];
    const float* g1   = (const float*)d_in[23]; const float* b1  = (const float*)d_in[24];
    const float* g2   = (const float*)d_in[25]; const float* b2  = (const float*)d_in[26];
    const float* g3   = (const float*)d_in[27]; const float* b3  = (const float*)d_in[28];
    float* out = (float*)d_out;

    cudaFuncSetAttribute(gemm_mma_k<0,4,true,true ,false,false,false>, cudaFuncAttributeMaxDynamicSharedMemorySize, SMEM_D);
    cudaFuncSetAttribute(gemm_mma_k<0,4,true,false,false,true ,false>, cudaFuncAttributeMaxDynamicSharedMemorySize, SMEM_D);
    cudaFuncSetAttribute(gemm_mma_k<0,4,true,false,false,false,false>, cudaFuncAttributeMaxDynamicSharedMemorySize, SMEM_D);
    cudaFuncSetAttribute(gemm_mma_k<1,4,true,true ,false,false,false>, cudaFuncAttributeMaxDynamicSharedMemorySize, SMEM_D);
    cudaFuncSetAttribute(gemm_mma_k<1,4,true,true ,true ,false,false>, cudaFuncAttributeMaxDynamicSharedMemorySize, SMEM_D);
    cudaFuncSetAttribute(gemm_mma_k<1,2,false,false,false,false,true >, cudaFuncAttributeMaxDynamicSharedMemorySize, SMEM_P);
    cudaFuncSetAttribute(gemm_mma_k<1,2,false,false,false,false,false>, cudaFuncAttributeMaxDynamicSharedMemorySize, SMEM_P);

    float *px,*pqkv,*py,*pt,*pf,*pp,*pwt,*pbias;
    cudaGetSymbolAddress((void**)&px, g_x);
    cudaGetSymbolAddress((void**)&pqkv, g_qkv);
    cudaGetSymbolAddress((void**)&py, g_y);
    cudaGetSymbolAddress((void**)&pt, g_t);
    cudaGetSymbolAddress((void**)&pf, g_f);
    cudaGetSymbolAddress((void**)&pp, g_p);
    cudaGetSymbolAddress((void**)&pwt, g_wt);
    cudaGetSymbolAddress((void**)&pbias, g_bias);

    const long DD = (long)DMODEL*DMODEL;
    const long DF = (long)DMODEL*FDIM;
    const long MD = (long)MROWS*DMODEL;

    float* pq = pqkv;
    float* pk = pqkv + MD;
    float* pv = pqkv + 2*MD;

    // Family order in g_wt: sq sk sv so cq ck cv co (each 12*DD), then f1T, f2T
    float* sqT = pwt + 0*12*DD;  float* skT = pwt + 12*DD;
    float* svT = pwt + 24*DD;    float* soT = pwt + 36*DD;
    float* cqT = pwt + 48*DD;    float* ckT = pwt + 60*DD;
    float* cvT = pwt + 72*DD;    float* coT = pwt + 84*DD;
    float* f1T = pwt + 96*DD;
    float* f2T = f1T + 12*DF;

    {
        dim3 blk(32, 8);
        transpose_k<<<dim3(16,16,NLAYERS), blk>>>(sqW, sqT, DMODEL, DMODEL);
        transpose_k<<<dim3(16,16,NLAYERS), blk>>>(skW, skT, DMODEL, DMODEL);
        transpose_k<<<dim3(16,16,NLAYERS), blk>>>(svW, svT, DMODEL, DMODEL);
        transpose_k<<<dim3(16,16,NLAYERS), blk>>>(soW, soT, DMODEL, DMODEL);
        transpose_k<<<dim3(16,16,NLAYERS), blk>>>(cqW, cqT, DMODEL, DMODEL);
        transpose_k<<<dim3(16,16,NLAYERS), blk>>>(ckW, ckT, DMODEL, DMODEL);
        transpose_k<<<dim3(16,16,NLAYERS), blk>>>(cvW, cvT, DMODEL, DMODEL);
        transpose_k<<<dim3(16,16,NLAYERS), blk>>>(coW, coT, DMODEL, DMODEL);
        transpose_k<<<dim3(64,16,NLAYERS), blk>>>(f1W, f1T, DMODEL, FDIM);
        transpose_k<<<dim3(16,64,NLAYERS), blk>>>(f2W, f2T, FDIM, DMODEL);
        packbias_k<<<(4*NLAYERS*DMODEL)/256, 256>>>(sqb, skb, ckb, cvb, pbias);
    }

    addpos_k<<<(MROWS*DMODEL)/256, 256>>>(xin, pos, px);

    const long LB = (long)NLAYERS*DMODEL;   // bias z-stride in packed buffer

    for (int l = 0; l < NLAYERS; l++) {
        // ---- self-attention (causal) ----
        // batched Q,K proj (tf32, exp-sensitive path)
        dense32(px, sqT + l*DD, pbias + l*DMODEL, pq,
                MROWS, DMODEL, DMODEL, 12*DD, MD, LB, 2);
        // V proj (bf16 value path)
        dense16(px, svT + l*DD, svb + l*DMODEL, pv, MROWS, DMODEL, DMODEL, false);
        qkt_gemm(pq, pk, pp, true);
        softmax_k<<<BATCH*NHEADS*SEQ, 256>>>(pp, 1);
        pv_gemm(pp, pv, py, true);
        dense16(py, soT + l*DD, sob + l*DMODEL, pt, MROWS, DMODEL, DMODEL, false);
        add_ln_k<<<MROWS, 128>>>(px, pt, g1 + l*DMODEL, b1 + l*DMODEL, px);

        // ---- cross-attention ----
        dense32(px, cqT + l*DD, cqb + l*DMODEL, pq,
                MROWS, DMODEL, DMODEL, 0, 0, 0, 1);
        // batched K,V proj from kv (tf32; ck exp-sensitive, cv rides along)
        dense32(kv, ckT + l*DD, pbias + 2*LB + l*DMODEL, pk,
                MROWS, DMODEL, DMODEL, 12*DD, MD, LB, 2);
        qkt_gemm(pq, pk, pp, false);
        softmax_k<<<BATCH*NHEADS*SEQ, 256>>>(pp, 0);
        pv_gemm(pp, pv, py, false);
        dense16(py, coT + l*DD, cob + l*DMODEL, pt, MROWS, DMODEL, DMODEL, false);
        add_ln_k<<<MROWS, 128>>>(px, pt, g2 + l*DMODEL, b2 + l*DMODEL, px);

        // ---- FFN (bf16 value path) ----
        dense16(px, f1T + l*DF, f1b + l*FDIM, pf, MROWS, FDIM, DMODEL, true);
        dense16(pf, f2T + l*DF, f2b + l*DMODEL, pt, MROWS, DMODEL, FDIM, false);
        add_ln_k<<<MROWS, 128>>>(px, pt, g3 + l*DMODEL, b3 + l*DMODEL,
                                 (l == NLAYERS-1) ? out : px);
    }
}

// round 9
// speedup vs baseline: 1.8565x; 1.0454x over previous
#include <cuda_runtime.h>
#include <cstdint>

// Problem constants
#define NLAYERS 12
#define BATCH   4
#define SEQ     1024
#define DMODEL  512
#define NHEADS  8
#define DHEAD   64
#define FDIM    2048
#define MROWS   (BATCH*SEQ)   // 4096

// ===========================================================================
// sm_80-level PTX helpers
// ===========================================================================
#define CP_ASYNC16(dst, src) \
    asm volatile("cp.async.cg.shared.global [%0], [%1], 16;" :: "r"(dst), "l"(src))
#define CP_COMMIT() asm volatile("cp.async.commit_group;" ::: "memory")
#define CP_WAIT0()  asm volatile("cp.async.wait_group 0;" ::: "memory")
#define CP_WAIT1()  asm volatile("cp.async.wait_group 1;" ::: "memory")

__device__ __forceinline__ void tf32_split(float x, uint32_t& hi, uint32_t& lo) {
    uint32_t h;
    asm("cvt.rna.tf32.f32 %0, %1;" : "=r"(h) : "f"(x));
    float r = x - __uint_as_float(h);
    uint32_t l;
    asm("cvt.rna.tf32.f32 %0, %1;" : "=r"(l) : "f"(r));
    hi = h; lo = l;
}

// Split two fp32 (k-adjacent pair) into packed bf16x2 hi and lo parts.
// Lower 16 bits hold x0 (even k), upper hold x1 (odd k).
__device__ __forceinline__ void bf16_split2(float x0, float x1,
                                            uint32_t& hi, uint32_t& lo) {
    uint32_t h;
    asm("cvt.rn.bf16x2.f32 %0, %1, %2;" : "=r"(h) : "f"(x1), "f"(x0));
    float h0 = __uint_as_float(h << 16);
    float h1 = __uint_as_float(h & 0xffff0000u);
    float r0 = x0 - h0, r1 = x1 - h1;
    uint32_t l;
    asm("cvt.rn.bf16x2.f32 %0, %1, %2;" : "=r"(l) : "f"(r1), "f"(r0));
    hi = h; lo = l;
}

__device__ __forceinline__ void mma8(float* c, const uint32_t* a, const uint32_t* b) {
    asm volatile(
        "mma.sync.aligned.m16n8k8.row.col.f32.tf32.tf32.f32 "
        "{%0,%1,%2,%3}, {%4,%5,%6,%7}, {%8,%9}, {%0,%1,%2,%3};"
        : "+f"(c[0]), "+f"(c[1]), "+f"(c[2]), "+f"(c[3])
        : "r"(a[0]), "r"(a[1]), "r"(a[2]), "r"(a[3]), "r"(b[0]), "r"(b[1]));
}

__device__ __forceinline__ void mma16(float* c, const uint32_t* a, const uint32_t* b) {
    asm volatile(
        "mma.sync.aligned.m16n8k16.row.col.f32.bf16.bf16.f32 "
        "{%0,%1,%2,%3}, {%4,%5,%6,%7}, {%8,%9}, {%0,%1,%2,%3};"
        : "+f"(c[0]), "+f"(c[1]), "+f"(c[2]), "+f"(c[3])
        : "r"(a[0]), "r"(a[1]), "r"(a[2]), "r"(a[3]), "r"(b[0]), "r"(b[1]));
}

// ===========================================================================
// Scratch (static device globals; no allocation anywhere)
// ===========================================================================
__device__ float g_x[MROWS*DMODEL];
__device__ float g_qkv[3L*MROWS*DMODEL];     // q, k, v slabs
__device__ float g_y[MROWS*DMODEL];
__device__ float g_t[MROWS*DMODEL];
__device__ float g_f[MROWS*FDIM];
__device__ float g_wt[96L*DMODEL*DMODEL + 24L*DMODEL*FDIM];  // transposed weights
__device__ float g_bias[4L*NLAYERS*DMODEL];  // packed biases: sq, sk, ck, cv

// ===========================================================================
// Weight transpose: Wt[b][c][r] = W[b][r][c]
// ===========================================================================
__global__ void transpose_k(const float* __restrict__ S, float* __restrict__ D,
                            int R, int C)
{
    __shared__ float t[32][33];
    const long b = blockIdx.z;
    S += b * (long)R * C;
    D += b * (long)R * C;
    const int c0 = blockIdx.x * 32, r0 = blockIdx.y * 32;
    const int tx = threadIdx.x, ty = threadIdx.y;
    #pragma unroll
    for (int i = 0; i < 32; i += 8)
        t[ty + i][tx] = S[(long)(r0 + ty + i)*C + c0 + tx];
    __syncthreads();
    #pragma unroll
    for (int i = 0; i < 32; i += 8)
        D[(long)(c0 + ty + i)*R + r0 + tx] = t[tx][ty + i];
}

__global__ void packbias_k(const float* __restrict__ a0, const float* __restrict__ a1,
                           const float* __restrict__ a2, const float* __restrict__ a3,
                           float* __restrict__ dst)
{
    const int i = blockIdx.x*256 + threadIdx.x;  // 4 * 12*512 = 24576
    const int f = i / (NLAYERS*DMODEL), r = i % (NLAYERS*DMODEL);
    const float* s = (f == 0) ? a0 : (f == 1) ? a1 : (f == 2) ? a2 : a3;
    dst[i] = s[r];
}

// ===========================================================================
// mma.sync GEMM — round-6 VALIDATED configuration (TB=true, transposed W).
// PREC 0 = 3xTF32, PREC 1 = 2xbf16. 256 threads, 8 warps 2x4, block 128x128,
// K-tile 16, cp.async double buffered. Batch z -> (zb, zh); sbz bias z-stride.
// ===========================================================================
template<int PREC, bool BIAS, bool RELU>
__global__ __launch_bounds__(256, 1) void gemm_mma_k(
    const float* __restrict__ A, const float* __restrict__ Bm,
    const float* __restrict__ bias, float* __restrict__ C,
    int K, int lda, int ldb, int ldc,
    long sBb, long sCb, long sbz)
{
    constexpr int AS   = 20;
    constexpr int BS   = 20;
    constexpr int ABUF = 128*AS;
    constexpr int BBUF = 128*BS;

    const int row0 = blockIdx.y * 128;
    const int col0 = blockIdx.x * 128;
    const int zb = blockIdx.z;
    Bm += (long)zb*sBb;
    C  += (long)zb*sCb;
    if (BIAS) bias += (long)zb*sbz;

    extern __shared__ float smf[];
    float* Asm = smf;
    float* Bsm = smf + 2*ABUF;

    const int tid  = threadIdx.x;
    const int wid  = tid >> 5;
    const int lane = tid & 31;
    const int g = lane >> 2, t = lane & 3;
    const int wm = (wid >> 2) * 64;
    const int wn = (wid & 3) * 32;

    const int ns = K >> 4;

    auto loadA = [&](int s) {
        float* dst = Asm + (s & 1) * ABUF;
        const int idx = tid;
        const int r  = idx >> 1;
        const int kc = (idx & 1) << 3;
        uint32_t d = (uint32_t)__cvta_generic_to_shared(dst + r*AS + kc);
        CP_ASYNC16(d, A + (long)(row0 + r)*lda + (s << 4) + kc);
        uint32_t d2 = (uint32_t)__cvta_generic_to_shared(dst + r*AS + kc + 4);
        CP_ASYNC16(d2, A + (long)(row0 + r)*lda + (s << 4) + kc + 4);
    };
    auto loadB = [&](int s) {
        float* dst = Bsm + (s & 1) * BBUF;
        const int idx = tid;
        const int r  = idx >> 1;
        const int kc = (idx & 1) << 3;
        uint32_t d = (uint32_t)__cvta_generic_to_shared(dst + r*BS + kc);
        CP_ASYNC16(d, Bm + (long)(col0 + r)*ldb + (s << 4) + kc);
        uint32_t d2 = (uint32_t)__cvta_generic_to_shared(dst + r*BS + kc + 4);
        CP_ASYNC16(d2, Bm + (long)(col0 + r)*ldb + (s << 4) + kc + 4);
    };

    float acc[4][4][4] = {};

    loadA(0); loadB(0); CP_COMMIT();

    for (int s = 0; s < ns; s++) {
        if (s + 1 < ns) { loadA(s+1); loadB(s+1); CP_COMMIT(); CP_WAIT1(); }
        else            { CP_WAIT0(); }
        __syncthreads();

        const float* a = Asm + (s & 1) * ABUF;
        const float* b = Bsm + (s & 1) * BBUF;

        if (PREC == 0) {
            #pragma unroll
            for (int kk = 0; kk < 16; kk += 8) {
                uint32_t ahi[4][4], alo[4][4];
                #pragma unroll
                for (int i = 0; i < 4; i++) {
                    const int m0 = wm + 16*i + g;
                    tf32_split(a[(m0    )*AS + kk + t    ], ahi[i][0], alo[i][0]);
                    tf32_split(a[(m0 + 8)*AS + kk + t    ], ahi[i][1], alo[i][1]);
                    tf32_split(a[(m0    )*AS + kk + t + 4], ahi[i][2], alo[i][2]);
                    tf32_split(a[(m0 + 8)*AS + kk + t + 4], ahi[i][3], alo[i][3]);
                }
                #pragma unroll
                for (int j = 0; j < 4; j++) {
                    const int n0 = wn + 8*j + g;
                    uint32_t bhi[2], blo[2];
                    tf32_split(b[n0*BS + kk + t    ], bhi[0], blo[0]);
                    tf32_split(b[n0*BS + kk + t + 4], bhi[1], blo[1]);
                    #pragma unroll
                    for (int i = 0; i < 4; i++) {
                        mma8(acc[i][j], ahi[i], bhi);
                        mma8(acc[i][j], ahi[i], blo);
                        mma8(acc[i][j], alo[i], bhi);
                    }
                }
            }
        } else {
            uint32_t ahi[4][4], alo[4][4];
            #pragma unroll
            for (int i = 0; i < 4; i++) {
                const int m0 = wm + 16*i + g;
                #pragma unroll
                for (int rr = 0; rr < 4; rr++) {
                    const int r  = m0 + ((rr & 1) << 3);
                    const int kc = 2*t + ((rr >> 1) << 3);
                    float2 x = *(const float2*)&a[r*AS + kc];
                    bf16_split2(x.x, x.y, ahi[i][rr], alo[i][rr]);
                }
            }
            #pragma unroll
            for (int j = 0; j < 4; j++) {
                const int n0 = wn + 8*j + g;
                uint32_t bhi[2], blo[2];
                #pragma unroll
                for (int rr = 0; rr < 2; rr++) {
                    const int kc = 2*t + (rr << 3);
                    float2 x = *(const float2*)&b[n0*BS + kc];
                    bf16_split2(x.x, x.y, bhi[rr], blo[rr]);
                }
                #pragma unroll
                for (int i = 0; i < 4; i++) {
                    mma16(acc[i][j], ahi[i], bhi);
                    mma16(acc[i][j], ahi[i], blo);
                    mma16(acc[i][j], alo[i], bhi);
                }
            }
        }
        __syncthreads();
    }

    #pragma unroll
    for (int j = 0; j < 4; j++) {
        const int cb = col0 + wn + 8*j + 2*t;
        float bx = 0.f, by = 0.f;
        if (BIAS) { bx = bias[cb]; by = bias[cb + 1]; }
        #pragma unroll
        for (int i = 0; i < 4; i++) {
            const int r = row0 + wm + 16*i + g;
            float2 v0, v1;
            v0.x = acc[i][j][0] + bx; v0.y = acc[i][j][1] + by;
            v1.x = acc[i][j][2] + bx; v1.y = acc[i][j][3] + by;
            if (RELU) {
                v0.x = fmaxf(v0.x, 0.f); v0.y = fmaxf(v0.y, 0.f);
                v1.x = fmaxf(v1.x, 0.f); v1.y = fmaxf(v1.y, 0.f);
            }
            *(float2*)&C[(long)r*ldc + cb]       = v0;
            *(float2*)&C[(long)(r + 8)*ldc + cb] = v1;
        }
    }
}

// ===========================================================================
// Flash attention (FIXED): P row stride 66 uint2 (64 needed + 2 pad).
// Single-buffered K/V (commit; wait0; sync). One CTA = 128 query rows of
// one (b,h). S via 3xTF32, online softmax, P packed bf16 hi/lo in SMEM,
// O += P@V via 3-term bf16.
// SMEM floats: Q 128x68 | K 128x68 | V 128x68 | P 128x66 uint2 | rm 512 | rs 512
// = 44032 floats = 176128 B
// ===========================================================================
#define TSF 68
#define PST 66
#define FLASH_SMEM 176128

template<bool CAUSAL>
__global__ __launch_bounds__(256, 1) void flash_k(
    const float* __restrict__ Qg, const float* __restrict__ Kg,
    const float* __restrict__ Vg, float* __restrict__ Yg)
{
    extern __shared__ float sm[];
    constexpr int QOFF  = 0;
    constexpr int KOFF  = 128*TSF;            // 8704
    constexpr int VOFF  = 2*128*TSF;          // 17408
    constexpr int POFF  = 3*128*TSF;          // 26112 (floats)
    constexpr int RMOFF = POFF + 128*PST*2;   // 43008
    constexpr int RSOFF = RMOFF + 512;        // 43520

    const int qb = blockIdx.x;
    const int bh = blockIdx.y;
    const long base = ((long)(bh >> 3)*SEQ)*DMODEL + (bh & 7)*DHEAD;
    const float* Kp = Kg + base;
    const float* Vp = Vg + base;

    const int tid = threadIdx.x;
    const int wid = tid >> 5, lane = tid & 31;
    const int g = lane >> 2, t = lane & 3;
    const int wy = wid >> 2, wx = wid & 3;    // 2 x 4 warp grid

    const int nb = CAUSAL ? (qb + 1) : (SEQ/128);

    auto load_tile = [&](int off, const float* src) {
        #pragma unroll
        for (int it = 0; it < 8; it++) {
            const int idx = tid + (it << 8);
            const int r = idx >> 4, c = (idx & 15) << 2;
            uint32_t d = (uint32_t)__cvta_generic_to_shared(sm + off + r*TSF + c);
            CP_ASYNC16(d, src + (long)r*DMODEL + c);
        }
    };

    load_tile(QOFF, Qg + base + (long)qb*128*DMODEL);
    CP_COMMIT();

    float m[8], l[8];
    #pragma unroll
    for (int s = 0; s < 8; s++) { m[s] = -1e30f; l[s] = 0.f; }
    float accO[4][2][4] = {};

    uint2* Pp = (uint2*)(sm + POFF);

    for (int n = 0; n < nb; n++) {
        __syncthreads();                        // prior consumers of K/V done
        load_tile(KOFF, Kp + (long)n*128*DMODEL);
        load_tile(VOFF, Vp + (long)n*128*DMODEL);
        CP_COMMIT();
        CP_WAIT0();
        __syncthreads();

        // ---- S = Q @ K^T (3xTF32) ----
        float accS[4][4][4] = {};
        #pragma unroll
        for (int kk = 0; kk < 64; kk += 8) {
            uint32_t ahi[4][4], alo[4][4];
            #pragma unroll
            for (int i = 0; i < 4; i++) {
                const int mb = wy*64 + 16*i + g;
                tf32_split(sm[QOFF + (mb    )*TSF + kk + t    ], ahi[i][0], alo[i][0]);
                tf32_split(sm[QOFF + (mb + 8)*TSF + kk + t    ], ahi[i][1], alo[i][1]);
                tf32_split(sm[QOFF + (mb    )*TSF + kk + t + 4], ahi[i][2], alo[i][2]);
                tf32_split(sm[QOFF + (mb + 8)*TSF + kk + t + 4], ahi[i][3], alo[i][3]);
            }
            #pragma unroll
            for (int j = 0; j < 4; j++) {
                const int n0 = wx*32 + 8*j + g;
                uint32_t bhi[2], blo[2];
                tf32_split(sm[KOFF + n0*TSF + kk + t    ], bhi[0], blo[0]);
                tf32_split(sm[KOFF + n0*TSF + kk + t + 4], bhi[1], blo[1]);
                #pragma unroll
                for (int i = 0; i < 4; i++) {
                    mma8(accS[i][j], ahi[i], bhi);
                    mma8(accS[i][j], ahi[i], blo);
                    mma8(accS[i][j], alo[i], bhi);
                }
            }
        }

        // ---- causal mask on diagonal block ----
        if (CAUSAL && n == qb) {
            #pragma unroll
            for (int i = 0; i < 4; i++) {
                const int r0 = wy*64 + 16*i + g;
                #pragma unroll
                for (int j = 0; j < 4; j++) {
                    const int c0 = wx*32 + 8*j + 2*t;
                    if (c0     > r0    ) accS[i][j][0] = -1e30f;
                    if (c0 + 1 > r0    ) accS[i][j][1] = -1e30f;
                    if (c0     > r0 + 8) accS[i][j][2] = -1e30f;
                    if (c0 + 1 > r0 + 8) accS[i][j][3] = -1e30f;
                }
            }
        }

        // ---- per-warp partial row max -> rm ----
        #pragma unroll
        for (int i = 0; i < 4; i++) {
            #pragma unroll
            for (int rh = 0; rh < 2; rh++) {
                float pm = -1e30f;
                #pragma unroll
                for (int j = 0; j < 4; j++)
                    pm = fmaxf(pm, fmaxf(accS[i][j][2*rh], accS[i][j][2*rh+1]));
                pm = fmaxf(pm, __shfl_xor_sync(0xffffffffu, pm, 1));
                pm = fmaxf(pm, __shfl_xor_sync(0xffffffffu, pm, 2));
                if (t == 0) sm[RMOFF + (wy*64 + 16*i + g + 8*rh)*4 + wx] = pm;
            }
        }
        __syncthreads();

        // ---- online softmax: rescale O/l, pack P (bf16 hi/lo), partial sums ----
        #pragma unroll
        for (int i = 0; i < 4; i++) {
            #pragma unroll
            for (int rh = 0; rh < 2; rh++) {
                const int s = 2*i + rh;
                const int row = wy*64 + 16*i + g + 8*rh;
                const float* rm = sm + RMOFF + row*4;
                float bm = fmaxf(fmaxf(rm[0], rm[1]), fmaxf(rm[2], rm[3]));
                float mnew = fmaxf(m[s], bm);
                float alpha = __expf((m[s] - mnew) * 0.125f);
                m[s] = mnew;
                l[s] *= alpha;
                #pragma unroll
                for (int j2 = 0; j2 < 2; j2++) {
                    accO[i][j2][2*rh  ] *= alpha;
                    accO[i][j2][2*rh+1] *= alpha;
                }
                float ps = 0.f;
                #pragma unroll
                for (int j = 0; j < 4; j++) {
                    float e0 = __expf((accS[i][j][2*rh  ] - mnew) * 0.125f);
                    float e1 = __expf((accS[i][j][2*rh+1] - mnew) * 0.125f);
                    ps += e0 + e1;
                    uint32_t hi, lo;
                    bf16_split2(e0, e1, hi, lo);
                    Pp[row*PST + wx*16 + 4*j + t] = make_uint2(hi, lo);
                }
                ps += __shfl_xor_sync(0xffffffffu, ps, 1);
                ps += __shfl_xor_sync(0xffffffffu, ps, 2);
                if (t == 0) sm[RSOFF + row*4 + wx] = ps;
            }
        }
        __syncthreads();

        #pragma unroll
        for (int i = 0; i < 4; i++)
            #pragma unroll
            for (int rh = 0; rh < 2; rh++) {
                const int row = wy*64 + 16*i + g + 8*rh;
                const float* rs = sm + RSOFF + row*4;
                l[2*i + rh] += rs[0] + rs[1] + rs[2] + rs[3];
            }

        // ---- O += P @ V (3-term bf16) ----
        #pragma unroll
        for (int kt = 0; kt < 8; kt++) {
            uint32_t pahi[4][4], palo[4][4];
            #pragma unroll
            for (int i = 0; i < 4; i++) {
                #pragma unroll
                for (int rr = 0; rr < 4; rr++) {
                    const int r  = wy*64 + 16*i + g + 8*(rr & 1);
                    const int kp = kt*8 + t + 4*(rr >> 1);
                    uint2 hl = Pp[r*PST + kp];
                    pahi[i][rr] = hl.x; palo[i][rr] = hl.y;
                }
            }
            #pragma unroll
            for (int j2 = 0; j2 < 2; j2++) {
                const int n0 = wx*16 + 8*j2 + g;
                uint32_t vh[2], vl[2];
                #pragma unroll
                for (int rr = 0; rr < 2; rr++) {
                    const int kc = kt*16 + 2*t + 8*rr;
                    bf16_split2(sm[VOFF + kc*TSF + n0], sm[VOFF + (kc+1)*TSF + n0],
                                vh[rr], vl[rr]);
                }
                #pragma unroll
                for (int i = 0; i < 4; i++) {
                    mma16(accO[i][j2], pahi[i], vh);
                    mma16(accO[i][j2], pahi[i], vl);
                    mma16(accO[i][j2], palo[i], vh);
                }
            }
        }
    }

    // ---- normalize and write O ----
    #pragma unroll
    for (int i = 0; i < 4; i++) {
        #pragma unroll
        for (int rh = 0; rh < 2; rh++) {
            const int row = wy*64 + 16*i + g + 8*rh;
            const float inv = 1.f / l[2*i + rh];
            #pragma unroll
            for (int j2 = 0; j2 < 2; j2++) {
                float2 v;
                v.x = accO[i][j2][2*rh  ] * inv;
                v.y = accO[i][j2][2*rh+1] * inv;
                *(float2*)&Yg[base + (long)(qb*128 + row)*DMODEL + wx*16 + 8*j2 + 2*t] = v;
            }
        }
    }
}

// ===========================================================================
// LayerNorm / pos-add
// ===========================================================================
__global__ void add_ln_k(const float* __restrict__ X, const float* __restrict__ Y,
                         const float* __restrict__ g, const float* __restrict__ b,
                         float* __restrict__ O)
{
    const long row = blockIdx.x;
    const float* x = X + row * DMODEL;
    const float* y = Y + row * DMODEL;
    float* o = O + row * DMODEL;
    const int t = threadIdx.x;
    __shared__ float sm[4];

    float v[4];
    float s = 0.f;
    #pragma unroll
    for (int i = 0; i < 4; i++) {
        int j = t + i*128;
        v[i] = x[j] + y[j];
        s += v[i];
    }
    #pragma unroll
    for (int o2 = 16; o2 > 0; o2 >>= 1) s += __shfl_xor_sync(0xffffffffu, s, o2);
    if ((t & 31) == 0) sm[t >> 5] = s;
    __syncthreads();
    const float mu = (sm[0]+sm[1]+sm[2]+sm[3]) * (1.f/DMODEL);
    __syncthreads();
    float var = 0.f;
    #pragma unroll
    for (int i = 0; i < 4; i++) { float d = v[i]-mu; var += d*d; }
    #pragma unroll
    for (int o2 = 16; o2 > 0; o2 >>= 1) var += __shfl_xor_sync(0xffffffffu, var, o2);
    if ((t & 31) == 0) sm[t >> 5] = var;
    __syncthreads();
    const float rs = rsqrtf((sm[0]+sm[1]+sm[2]+sm[3]) * (1.f/DMODEL) + 1e-5f);
    #pragma unroll
    for (int i = 0; i < 4; i++) {
        int j = t + i*128;
        o[j] = (v[i]-mu)*rs*g[j] + b[j];
    }
}

__global__ void addpos_k(const float* __restrict__ x, const float* __restrict__ pos,
                         float* __restrict__ o)
{
    long idx = (long)blockIdx.x * 256 + threadIdx.x;
    long sd  = idx % ((long)SEQ * DMODEL);
    o[idx] = x[idx] + pos[sd];
}

// ===========================================================================
// Host-side launch helpers (round-6 validated dense config)
// ===========================================================================
static const int SMEM_D = 2*(128*20 + 128*20)*4;   // 40960 B

static void dense32(const float* A, const float* Bt, const float* bias, float* C,
                    int M, int N, int K, long sBb, long sCb, long sbz, int nz)
{
    dim3 grid(N/128, M/128, nz);
    gemm_mma_k<0,true,false><<<grid,256,SMEM_D>>>(A,Bt,bias,C,K, K,K,N, sBb,sCb,sbz);
}
static void dense16(const float* A, const float* Bt, const float* bias, float* C,
                    int M, int N, int K, bool relu)
{
    dim3 grid(N/128, M/128, 1);
    if (relu)
        gemm_mma_k<1,true,true ><<<grid,256,SMEM_D>>>(A,Bt,bias,C,K, K,K,N, 0,0,0);
    else
        gemm_mma_k<1,true,false><<<grid,256,SMEM_D>>>(A,Bt,bias,C,K, K,K,N, 0,0,0);
}

extern "C" void kernel_launch(void* const* d_in, const int* in_sizes, int n_in,
                              void* d_out, int out_size)
{
    const float* kv   = (const float*)d_in[0];
    const float* xin  = (const float*)d_in[1];
    const float* pos  = (const float*)d_in[2];
    const float* sqW  = (const float*)d_in[3];  const float* sqb = (const float*)d_in[4];
    const float* skW  = (const float*)d_in[5];  const float* skb = (const float*)d_in[6];
    const float* svW  = (const float*)d_in[7];  const float* svb = (const float*)d_in[8];
    const float* soW  = (const float*)d_in[9];  const float* sob = (const float*)d_in[10];
    const float* cqW  = (const float*)d_in[11]; const float* cqb = (const float*)d_in[12];
    const float* ckW  = (const float*)d_in[13]; const float* ckb = (const float*)d_in[14];
    const float* cvW  = (const float*)d_in[15]; const float* cvb = (const float*)d_in[16];
    const float* coW  = (const float*)d_in[17]; const float* cob = (const float*)d_in[18];
    const float* f1W  = (const float*)d_in[19]; const float* f1b = (const float*)d_in[20];
    const float* f2W  = (const float*)d_in[21]; const float* f2b = (const float*)d_in[22];
    const float* g1   = (const float*)d_in[23]; const float* b1  = (const float*)d_in[24];
    const float* g2   = (const float*)d_in[25]; const float* b2  = (const float*)d_in[26];
    const float* g3   = (const float*)d_in[27]; const float* b3  = (const float*)d_in[28];
    float* out = (float*)d_out;

    cudaFuncSetAttribute(gemm_mma_k<0,true,false>, cudaFuncAttributeMaxDynamicSharedMemorySize, SMEM_D);
    cudaFuncSetAttribute(gemm_mma_k<1,true,false>, cudaFuncAttributeMaxDynamicSharedMemorySize, SMEM_D);
    cudaFuncSetAttribute(gemm_mma_k<1,true,true >, cudaFuncAttributeMaxDynamicSharedMemorySize, SMEM_D);
    cudaFuncSetAttribute(flash_k<true >, cudaFuncAttributeMaxDynamicSharedMemorySize, FLASH_SMEM);
    cudaFuncSetAttribute(flash_k<false>, cudaFuncAttributeMaxDynamicSharedMemorySize, FLASH_SMEM);

    float *px,*pqkv,*py,*pt,*pf,*pwt,*pbias;
    cudaGetSymbolAddress((void**)&px, g_x);
    cudaGetSymbolAddress((void**)&pqkv, g_qkv);
    cudaGetSymbolAddress((void**)&py, g_y);
    cudaGetSymbolAddress((void**)&pt, g_t);
    cudaGetSymbolAddress((void**)&pf, g_f);
    cudaGetSymbolAddress((void**)&pwt, g_wt);
    cudaGetSymbolAddress((void**)&pbias, g_bias);

    const long DD = (long)DMODEL*DMODEL;
    const long DF = (long)DMODEL*FDIM;
    const long MD = (long)MROWS*DMODEL;

    float* pq = pqkv;
    float* pk = pqkv + MD;
    float* pv = pqkv + 2*MD;

    float* sqT = pwt + 0*12*DD;  float* skT = pwt + 12*DD;
    float* svT = pwt + 24*DD;    float* soT = pwt + 36*DD;
    float* cqT = pwt + 48*DD;    float* ckT = pwt + 60*DD;
    float* cvT = pwt + 72*DD;    float* coT = pwt + 84*DD;
    float* f1T = pwt + 96*DD;            // [L][FDIM][DMODEL]
    float* f2T = f1T + 12*DF;            // [L][DMODEL][FDIM]

    {
        dim3 blk(32, 8);
        transpose_k<<<dim3(16,16,NLAYERS), blk>>>(sqW, sqT, DMODEL, DMODEL);
        transpose_k<<<dim3(16,16,NLAYERS), blk>>>(skW, skT, DMODEL, DMODEL);
        transpose_k<<<dim3(16,16,NLAYERS), blk>>>(svW, svT, DMODEL, DMODEL);
        transpose_k<<<dim3(16,16,NLAYERS), blk>>>(soW, soT, DMODEL, DMODEL);
        transpose_k<<<dim3(16,16,NLAYERS), blk>>>(cqW, cqT, DMODEL, DMODEL);
        transpose_k<<<dim3(16,16,NLAYERS), blk>>>(ckW, ckT, DMODEL, DMODEL);
        transpose_k<<<dim3(16,16,NLAYERS), blk>>>(cvW, cvT, DMODEL, DMODEL);
        transpose_k<<<dim3(16,16,NLAYERS), blk>>>(coW, coT, DMODEL, DMODEL);
        transpose_k<<<dim3(64,16,NLAYERS), blk>>>(f1W, f1T, DMODEL, FDIM);
        transpose_k<<<dim3(16,64,NLAYERS), blk>>>(f2W, f2T, FDIM, DMODEL);
        packbias_k<<<(4*NLAYERS*DMODEL)/256, 256>>>(sqb, skb, ckb, cvb, pbias);
    }

    addpos_k<<<(MROWS*DMODEL)/256, 256>>>(xin, pos, px);

    const long LB = (long)NLAYERS*DMODEL;
    const dim3 fgrid(SEQ/128, BATCH*NHEADS);

    for (int l = 0; l < NLAYERS; l++) {
        // ---- self-attention (causal) ----
        dense32(px, sqT + l*DD, pbias + l*DMODEL, pq,
                MROWS, DMODEL, DMODEL, 12*DD, MD, LB, 2);      // Q and K batched
        dense16(px, svT + l*DD, svb + l*DMODEL, pv, MROWS, DMODEL, DMODEL, false);
        flash_k<true ><<<fgrid, 256, FLASH_SMEM>>>(pq, pk, pv, py);
        dense16(py, soT + l*DD, sob + l*DMODEL, pt, MROWS, DMODEL, DMODEL, false);
        add_ln_k<<<MROWS, 128>>>(px, pt, g1 + l*DMODEL, b1 + l*DMODEL, px);

        // ---- cross-attention ----
        dense32(px, cqT + l*DD, cqb + l*DMODEL, pq,
                MROWS, DMODEL, DMODEL, 0, 0, 0, 1);
        dense32(kv, ckT + l*DD, pbias + 2*LB + l*DMODEL, pk,
                MROWS, DMODEL, DMODEL, 12*DD, MD, LB, 2);      // K and V batched
        flash_k<false><<<fgrid, 256, FLASH_SMEM>>>(pq, pk, pv, py);
        dense16(py, coT + l*DD, cob + l*DMODEL, pt, MROWS, DMODEL, DMODEL, false);
        add_ln_k<<<MROWS, 128>>>(px, pt, g2 + l*DMODEL, b2 + l*DMODEL, px);

        // ---- FFN ----
        dense16(px, f1T + l*DF, f1b + l*FDIM, pf, MROWS, FDIM, DMODEL, true);
        dense16(pf, f2T + l*DF, f2b + l*DMODEL, pt, MROWS, DMODEL, FDIM, false);
        add_ln_k<<<MROWS, 128>>>(px, pt, g3 + l*DMODEL, b3 + l*DMODEL,
                                 (l == NLAYERS-1) ? out : px);
    }
}

// round 10
// speedup vs baseline: 1.8676x; 1.0060x over previous
#include <cuda_runtime.h>
#include <cstdint>

// Problem constants
#define NLAYERS 12
#define BATCH   4
#define SEQ     1024
#define DMODEL  512
#define NHEADS  8
#define DHEAD   64
#define FDIM    2048
#define MROWS   (BATCH*SEQ)   // 4096

// ===========================================================================
// sm_80-level PTX helpers
// ===========================================================================
#define CP_ASYNC16(dst, src) \
    asm volatile("cp.async.cg.shared.global [%0], [%1], 16;" :: "r"(dst), "l"(src))
#define CP_COMMIT() asm volatile("cp.async.commit_group;" ::: "memory")
#define CP_WAIT0()  asm volatile("cp.async.wait_group 0;" ::: "memory")
#define CP_WAIT1()  asm volatile("cp.async.wait_group 1;" ::: "memory")

__device__ __forceinline__ void tf32_split(float x, uint32_t& hi, uint32_t& lo) {
    uint32_t h;
    asm("cvt.rna.tf32.f32 %0, %1;" : "=r"(h) : "f"(x));
    float r = x - __uint_as_float(h);
    uint32_t l;
    asm("cvt.rna.tf32.f32 %0, %1;" : "=r"(l) : "f"(r));
    hi = h; lo = l;
}

// Split two fp32 (k-adjacent pair) into packed bf16x2 hi and lo parts.
// Lower 16 bits hold x0 (even k), upper hold x1 (odd k).
__device__ __forceinline__ void bf16_split2(float x0, float x1,
                                            uint32_t& hi, uint32_t& lo) {
    uint32_t h;
    asm("cvt.rn.bf16x2.f32 %0, %1, %2;" : "=r"(h) : "f"(x1), "f"(x0));
    float h0 = __uint_as_float(h << 16);
    float h1 = __uint_as_float(h & 0xffff0000u);
    float r0 = x0 - h0, r1 = x1 - h1;
    uint32_t l;
    asm("cvt.rn.bf16x2.f32 %0, %1, %2;" : "=r"(l) : "f"(r1), "f"(r0));
    hi = h; lo = l;
}

__device__ __forceinline__ void mma8(float* c, const uint32_t* a, const uint32_t* b) {
    asm volatile(
        "mma.sync.aligned.m16n8k8.row.col.f32.tf32.tf32.f32 "
        "{%0,%1,%2,%3}, {%4,%5,%6,%7}, {%8,%9}, {%0,%1,%2,%3};"
        : "+f"(c[0]), "+f"(c[1]), "+f"(c[2]), "+f"(c[3])
        : "r"(a[0]), "r"(a[1]), "r"(a[2]), "r"(a[3]), "r"(b[0]), "r"(b[1]));
}

__device__ __forceinline__ void mma16(float* c, const uint32_t* a, const uint32_t* b) {
    asm volatile(
        "mma.sync.aligned.m16n8k16.row.col.f32.bf16.bf16.f32 "
        "{%0,%1,%2,%3}, {%4,%5,%6,%7}, {%8,%9}, {%0,%1,%2,%3};"
        : "+f"(c[0]), "+f"(c[1]), "+f"(c[2]), "+f"(c[3])
        : "r"(a[0]), "r"(a[1]), "r"(a[2]), "r"(a[3]), "r"(b[0]), "r"(b[1]));
}

// ===========================================================================
// Scratch (static device globals; no allocation anywhere)
// ===========================================================================
__device__ float g_x[MROWS*DMODEL];
__device__ float g_qkv[3L*MROWS*DMODEL];     // q, k, v slabs
__device__ float g_y[MROWS*DMODEL];
__device__ float g_t[MROWS*DMODEL];
__device__ float g_f[MROWS*FDIM];
__device__ float g_wt[96L*DMODEL*DMODEL + 24L*DMODEL*FDIM];  // transposed weights
__device__ float g_bias[4L*NLAYERS*DMODEL];  // packed biases: sq, sk, ck, cv

// ===========================================================================
// Weight transposes.
// transpose8_k: all 8 DxD weight families in ONE launch (grid.z = 96).
// transpose_k: generic (for f1 / f2 shapes).
// ===========================================================================
__global__ void transpose8_k(const float* __restrict__ s0, const float* __restrict__ s1,
                             const float* __restrict__ s2, const float* __restrict__ s3,
                             const float* __restrict__ s4, const float* __restrict__ s5,
                             const float* __restrict__ s6, const float* __restrict__ s7,
                             float* __restrict__ dstBase)
{
    __shared__ float t[32][33];
    const int z = blockIdx.z;
    const int f = z / NLAYERS, ly = z % NLAYERS;
    const float* S =
        (f == 0) ? s0 : (f == 1) ? s1 : (f == 2) ? s2 : (f == 3) ? s3 :
        (f == 4) ? s4 : (f == 5) ? s5 : (f == 6) ? s6 : s7;
    const long DD = (long)DMODEL*DMODEL;
    S += (long)ly * DD;
    float* D = dstBase + (long)f*NLAYERS*DD + (long)ly*DD;

    const int c0 = blockIdx.x * 32, r0 = blockIdx.y * 32;
    const int tx = threadIdx.x, ty = threadIdx.y;
    #pragma unroll
    for (int i = 0; i < 32; i += 8)
        t[ty + i][tx] = S[(long)(r0 + ty + i)*DMODEL + c0 + tx];
    __syncthreads();
    #pragma unroll
    for (int i = 0; i < 32; i += 8)
        D[(long)(c0 + ty + i)*DMODEL + r0 + tx] = t[tx][ty + i];
}

__global__ void transpose_k(const float* __restrict__ S, float* __restrict__ D,
                            int R, int C)
{
    __shared__ float t[32][33];
    const long b = blockIdx.z;
    S += b * (long)R * C;
    D += b * (long)R * C;
    const int c0 = blockIdx.x * 32, r0 = blockIdx.y * 32;
    const int tx = threadIdx.x, ty = threadIdx.y;
    #pragma unroll
    for (int i = 0; i < 32; i += 8)
        t[ty + i][tx] = S[(long)(r0 + ty + i)*C + c0 + tx];
    __syncthreads();
    #pragma unroll
    for (int i = 0; i < 32; i += 8)
        D[(long)(c0 + ty + i)*R + r0 + tx] = t[tx][ty + i];
}

__global__ void packbias_k(const float* __restrict__ a0, const float* __restrict__ a1,
                           const float* __restrict__ a2, const float* __restrict__ a3,
                           float* __restrict__ dst)
{
    const int i = blockIdx.x*256 + threadIdx.x;  // 4 * 12*512 = 24576
    const int f = i / (NLAYERS*DMODEL), r = i % (NLAYERS*DMODEL);
    const float* s = (f == 0) ? a0 : (f == 1) ? a1 : (f == 2) ? a2 : a3;
    dst[i] = s[r];
}

// ===========================================================================
// mma.sync GEMM — validated configuration (TB=true, transposed W).
// PREC 0 = 3xTF32, PREC 1 = 2xbf16. 256 threads, 8 warps 2x4, block 128x128,
// K-tile 16, cp.async double buffered. Batch over z; sbz bias z-stride.
// ===========================================================================
template<int PREC, bool BIAS, bool RELU>
__global__ __launch_bounds__(256, 1) void gemm_mma_k(
    const float* __restrict__ A, const float* __restrict__ Bm,
    const float* __restrict__ bias, float* __restrict__ C,
    int K, int lda, int ldb, int ldc,
    long sBb, long sCb, long sbz)
{
    constexpr int AS   = 20;
    constexpr int BS   = 20;
    constexpr int ABUF = 128*AS;
    constexpr int BBUF = 128*BS;

    const int row0 = blockIdx.y * 128;
    const int col0 = blockIdx.x * 128;
    const int zb = blockIdx.z;
    Bm += (long)zb*sBb;
    C  += (long)zb*sCb;
    if (BIAS) bias += (long)zb*sbz;

    extern __shared__ float smf[];
    float* Asm = smf;
    float* Bsm = smf + 2*ABUF;

    const int tid  = threadIdx.x;
    const int wid  = tid >> 5;
    const int lane = tid & 31;
    const int g = lane >> 2, t = lane & 3;
    const int wm = (wid >> 2) * 64;
    const int wn = (wid & 3) * 32;

    const int ns = K >> 4;

    auto loadA = [&](int s) {
        float* dst = Asm + (s & 1) * ABUF;
        const int r  = tid >> 1;
        const int kc = (tid & 1) << 3;
        uint32_t d = (uint32_t)__cvta_generic_to_shared(dst + r*AS + kc);
        CP_ASYNC16(d, A + (long)(row0 + r)*lda + (s << 4) + kc);
        uint32_t d2 = (uint32_t)__cvta_generic_to_shared(dst + r*AS + kc + 4);
        CP_ASYNC16(d2, A + (long)(row0 + r)*lda + (s << 4) + kc + 4);
    };
    auto loadB = [&](int s) {
        float* dst = Bsm + (s & 1) * BBUF;
        const int r  = tid >> 1;
        const int kc = (tid & 1) << 3;
        uint32_t d = (uint32_t)__cvta_generic_to_shared(dst + r*BS + kc);
        CP_ASYNC16(d, Bm + (long)(col0 + r)*ldb + (s << 4) + kc);
        uint32_t d2 = (uint32_t)__cvta_generic_to_shared(dst + r*BS + kc + 4);
        CP_ASYNC16(d2, Bm + (long)(col0 + r)*ldb + (s << 4) + kc + 4);
    };

    float acc[4][4][4] = {};

    loadA(0); loadB(0); CP_COMMIT();

    for (int s = 0; s < ns; s++) {
        if (s + 1 < ns) { loadA(s+1); loadB(s+1); CP_COMMIT(); CP_WAIT1(); }
        else            { CP_WAIT0(); }
        __syncthreads();

        const float* a = Asm + (s & 1) * ABUF;
        const float* b = Bsm + (s & 1) * BBUF;

        if (PREC == 0) {
            #pragma unroll
            for (int kk = 0; kk < 16; kk += 8) {
                uint32_t ahi[4][4], alo[4][4];
                #pragma unroll
                for (int i = 0; i < 4; i++) {
                    const int m0 = wm + 16*i + g;
                    tf32_split(a[(m0    )*AS + kk + t    ], ahi[i][0], alo[i][0]);
                    tf32_split(a[(m0 + 8)*AS + kk + t    ], ahi[i][1], alo[i][1]);
                    tf32_split(a[(m0    )*AS + kk + t + 4], ahi[i][2], alo[i][2]);
                    tf32_split(a[(m0 + 8)*AS + kk + t + 4], ahi[i][3], alo[i][3]);
                }
                #pragma unroll
                for (int j = 0; j < 4; j++) {
                    const int n0 = wn + 8*j + g;
                    uint32_t bhi[2], blo[2];
                    tf32_split(b[n0*BS + kk + t    ], bhi[0], blo[0]);
                    tf32_split(b[n0*BS + kk + t + 4], bhi[1], blo[1]);
                    #pragma unroll
                    for (int i = 0; i < 4; i++) {
                        mma8(acc[i][j], ahi[i], bhi);
                        mma8(acc[i][j], ahi[i], blo);
                        mma8(acc[i][j], alo[i], bhi);
                    }
                }
            }
        } else {
            uint32_t ahi[4][4], alo[4][4];
            #pragma unroll
            for (int i = 0; i < 4; i++) {
                const int m0 = wm + 16*i + g;
                #pragma unroll
                for (int rr = 0; rr < 4; rr++) {
                    const int r  = m0 + ((rr & 1) << 3);
                    const int kc = 2*t + ((rr >> 1) << 3);
                    float2 x = *(const float2*)&a[r*AS + kc];
                    bf16_split2(x.x, x.y, ahi[i][rr], alo[i][rr]);
                }
            }
            #pragma unroll
            for (int j = 0; j < 4; j++) {
                const int n0 = wn + 8*j + g;
                uint32_t bhi[2], blo[2];
                #pragma unroll
                for (int rr = 0; rr < 2; rr++) {
                    const int kc = 2*t + (rr << 3);
                    float2 x = *(const float2*)&b[n0*BS + kc];
                    bf16_split2(x.x, x.y, bhi[rr], blo[rr]);
                }
                #pragma unroll
                for (int i = 0; i < 4; i++) {
                    mma16(acc[i][j], ahi[i], bhi);
                    mma16(acc[i][j], ahi[i], blo);
                    mma16(acc[i][j], alo[i], bhi);
                }
            }
        }
        __syncthreads();
    }

    #pragma unroll
    for (int j = 0; j < 4; j++) {
        const int cb = col0 + wn + 8*j + 2*t;
        float bx = 0.f, by = 0.f;
        if (BIAS) { bx = bias[cb]; by = bias[cb + 1]; }
        #pragma unroll
        for (int i = 0; i < 4; i++) {
            const int r = row0 + wm + 16*i + g;
            float2 v0, v1;
            v0.x = acc[i][j][0] + bx; v0.y = acc[i][j][1] + by;
            v1.x = acc[i][j][2] + bx; v1.y = acc[i][j][3] + by;
            if (RELU) {
                v0.x = fmaxf(v0.x, 0.f); v0.y = fmaxf(v0.y, 0.f);
                v1.x = fmaxf(v1.x, 0.f); v1.y = fmaxf(v1.y, 0.f);
            }
            *(float2*)&C[(long)r*ldc + cb]       = v0;
            *(float2*)&C[(long)(r + 8)*ldc + cb] = v1;
        }
    }
}

// ===========================================================================
// Flash attention, pipelined: K double-buffered, V single-buffered.
// Schedule per key-block n:
//   [commit K(n+1)] -> wait_group(1 if pending K else 0) -> sync
//   -> S = Q@K(n) -> mask -> softmax/P -> PV(V(n)) -> sync -> [commit V(n+1)]
// Group-FIFO invariant: at each wait, the only possibly-pending group is the
// just-committed K(n+1); Q/K(n)/V(n) groups are strictly older.
// SMEM floats: Q 128x68 | K 2x128x68 | V 128x68 | P 128x66 uint2 | rm 512 | rs 512
// = 52736 floats = 210944 B
// ===========================================================================
#define TSF 68
#define PST 66
#define FLASH_SMEM 210944

template<bool CAUSAL>
__global__ __launch_bounds__(256, 1) void flash_k(
    const float* __restrict__ Qg, const float* __restrict__ Kg,
    const float* __restrict__ Vg, float* __restrict__ Yg)
{
    extern __shared__ float sm[];
    constexpr int QOFF  = 0;
    constexpr int KOFF  = 128*TSF;            // 8704 (2 buffers)
    constexpr int VOFF  = 3*128*TSF;          // 26112
    constexpr int POFF  = 4*128*TSF;          // 34816 (floats)
    constexpr int RMOFF = POFF + 128*PST*2;   // 51712
    constexpr int RSOFF = RMOFF + 512;        // 52224

    const int qb = blockIdx.x;
    const int bh = blockIdx.y;
    const long base = ((long)(bh >> 3)*SEQ)*DMODEL + (bh & 7)*DHEAD;
    const float* Kp = Kg + base;
    const float* Vp = Vg + base;

    const int tid = threadIdx.x;
    const int wid = tid >> 5, lane = tid & 31;
    const int g = lane >> 2, t = lane & 3;
    const int wy = wid >> 2, wx = wid & 3;    // 2 x 4 warp grid

    const int nb = CAUSAL ? (qb + 1) : (SEQ/128);

    auto load_tile = [&](int off, const float* src) {
        #pragma unroll
        for (int it = 0; it < 8; it++) {
            const int idx = tid + (it << 8);
            const int r = idx >> 4, c = (idx & 15) << 2;
            uint32_t d = (uint32_t)__cvta_generic_to_shared(sm + off + r*TSF + c);
            CP_ASYNC16(d, src + (long)r*DMODEL + c);
        }
    };

    // G0 = {Q, K0, V0}
    load_tile(QOFF, Qg + base + (long)qb*128*DMODEL);
    load_tile(KOFF, Kp);
    load_tile(VOFF, Vp);
    CP_COMMIT();

    float m[8], l[8];
    #pragma unroll
    for (int s = 0; s < 8; s++) { m[s] = -1e30f; l[s] = 0.f; }
    float accO[4][2][4] = {};

    uint2* Pp = (uint2*)(sm + POFF);

    for (int n = 0; n < nb; n++) {
        // Prefetch next K into the other buffer (last read by S(n-1), fenced).
        if (n + 1 < nb) {
            load_tile(KOFF + ((n+1)&1)*128*TSF, Kp + (long)(n+1)*128*DMODEL);
            CP_COMMIT();
            CP_WAIT1();     // K(n), V(n), Q groups are older than K(n+1)
        } else {
            CP_WAIT0();
        }
        __syncthreads();

        // ---- S = Q @ K^T (3xTF32) ----
        float accS[4][4][4] = {};
        const float* kb = sm + KOFF + (n&1)*128*TSF;
        #pragma unroll
        for (int kk = 0; kk < 64; kk += 8) {
            uint32_t ahi[4][4], alo[4][4];
            #pragma unroll
            for (int i = 0; i < 4; i++) {
                const int mb = wy*64 + 16*i + g;
                tf32_split(sm[QOFF + (mb    )*TSF + kk + t    ], ahi[i][0], alo[i][0]);
                tf32_split(sm[QOFF + (mb + 8)*TSF + kk + t    ], ahi[i][1], alo[i][1]);
                tf32_split(sm[QOFF + (mb    )*TSF + kk + t + 4], ahi[i][2], alo[i][2]);
                tf32_split(sm[QOFF + (mb + 8)*TSF + kk + t + 4], ahi[i][3], alo[i][3]);
            }
            #pragma unroll
            for (int j = 0; j < 4; j++) {
                const int n0 = wx*32 + 8*j + g;
                uint32_t bhi[2], blo[2];
                tf32_split(kb[n0*TSF + kk + t    ], bhi[0], blo[0]);
                tf32_split(kb[n0*TSF + kk + t + 4], bhi[1], blo[1]);
                #pragma unroll
                for (int i = 0; i < 4; i++) {
                    mma8(accS[i][j], ahi[i], bhi);
                    mma8(accS[i][j], ahi[i], blo);
                    mma8(accS[i][j], alo[i], bhi);
                }
            }
        }

        // ---- causal mask on diagonal block ----
        if (CAUSAL && n == qb) {
            #pragma unroll
            for (int i = 0; i < 4; i++) {
                const int r0 = wy*64 + 16*i + g;
                #pragma unroll
                for (int j = 0; j < 4; j++) {
                    const int c0 = wx*32 + 8*j + 2*t;
                    if (c0     > r0    ) accS[i][j][0] = -1e30f;
                    if (c0 + 1 > r0    ) accS[i][j][1] = -1e30f;
                    if (c0     > r0 + 8) accS[i][j][2] = -1e30f;
                    if (c0 + 1 > r0 + 8) accS[i][j][3] = -1e30f;
                }
            }
        }

        // ---- per-warp partial row max -> rm ----
        #pragma unroll
        for (int i = 0; i < 4; i++) {
            #pragma unroll
            for (int rh = 0; rh < 2; rh++) {
                float pm = -1e30f;
                #pragma unroll
                for (int j = 0; j < 4; j++)
                    pm = fmaxf(pm, fmaxf(accS[i][j][2*rh], accS[i][j][2*rh+1]));
                pm = fmaxf(pm, __shfl_xor_sync(0xffffffffu, pm, 1));
                pm = fmaxf(pm, __shfl_xor_sync(0xffffffffu, pm, 2));
                if (t == 0) sm[RMOFF + (wy*64 + 16*i + g + 8*rh)*4 + wx] = pm;
            }
        }
        __syncthreads();

        // ---- online softmax: rescale O/l, pack P (bf16 hi/lo), partial sums ----
        #pragma unroll
        for (int i = 0; i < 4; i++) {
            #pragma unroll
            for (int rh = 0; rh < 2; rh++) {
                const int s = 2*i + rh;
                const int row = wy*64 + 16*i + g + 8*rh;
                const float* rm = sm + RMOFF + row*4;
                float bm = fmaxf(fmaxf(rm[0], rm[1]), fmaxf(rm[2], rm[3]));
                float mnew = fmaxf(m[s], bm);
                float alpha = __expf((m[s] - mnew) * 0.125f);
                m[s] = mnew;
                l[s] *= alpha;
                #pragma unroll
                for (int j2 = 0; j2 < 2; j2++) {
                    accO[i][j2][2*rh  ] *= alpha;
                    accO[i][j2][2*rh+1] *= alpha;
                }
                float ps = 0.f;
                #pragma unroll
                for (int j = 0; j < 4; j++) {
                    float e0 = __expf((accS[i][j][2*rh  ] - mnew) * 0.125f);
                    float e1 = __expf((accS[i][j][2*rh+1] - mnew) * 0.125f);
                    ps += e0 + e1;
                    uint32_t hi, lo;
                    bf16_split2(e0, e1, hi, lo);
                    Pp[row*PST + wx*16 + 4*j + t] = make_uint2(hi, lo);
                }
                ps += __shfl_xor_sync(0xffffffffu, ps, 1);
                ps += __shfl_xor_sync(0xffffffffu, ps, 2);
                if (t == 0) sm[RSOFF + row*4 + wx] = ps;
            }
        }
        __syncthreads();

        #pragma unroll
        for (int i = 0; i < 4; i++)
            #pragma unroll
            for (int rh = 0; rh < 2; rh++) {
                const int row = wy*64 + 16*i + g + 8*rh;
                const float* rs = sm + RSOFF + row*4;
                l[2*i + rh] += rs[0] + rs[1] + rs[2] + rs[3];
            }

        // ---- O += P @ V (3-term bf16) ----
        #pragma unroll
        for (int kt = 0; kt < 8; kt++) {
            uint32_t pahi[4][4], palo[4][4];
            #pragma unroll
            for (int i = 0; i < 4; i++) {
                #pragma unroll
                for (int rr = 0; rr < 4; rr++) {
                    const int r  = wy*64 + 16*i + g + 8*(rr & 1);
                    const int kp = kt*8 + t + 4*(rr >> 1);
                    uint2 hl = Pp[r*PST + kp];
                    pahi[i][rr] = hl.x; palo[i][rr] = hl.y;
                }
            }
            #pragma unroll
            for (int j2 = 0; j2 < 2; j2++) {
                const int n0 = wx*16 + 8*j2 + g;
                uint32_t vh[2], vl[2];
                #pragma unroll
                for (int rr = 0; rr < 2; rr++) {
                    const int kc = kt*16 + 2*t + 8*rr;
                    bf16_split2(sm[VOFF + kc*TSF + n0], sm[VOFF + (kc+1)*TSF + n0],
                                vh[rr], vl[rr]);
                }
                #pragma unroll
                for (int i = 0; i < 4; i++) {
                    mma16(accO[i][j2], pahi[i], vh);
                    mma16(accO[i][j2], pahi[i], vl);
                    mma16(accO[i][j2], palo[i], vh);
                }
            }
        }

        // All warps done reading V(n); prefetch V(n+1) into the single buffer.
        __syncthreads();
        if (n + 1 < nb) {
            load_tile(VOFF, Vp + (long)(n+1)*128*DMODEL);
            CP_COMMIT();
        }
    }

    // ---- normalize and write O ----
    #pragma unroll
    for (int i = 0; i < 4; i++) {
        #pragma unroll
        for (int rh = 0; rh < 2; rh++) {
            const int row = wy*64 + 16*i + g + 8*rh;
            const float inv = 1.f / l[2*i + rh];
            #pragma unroll
            for (int j2 = 0; j2 < 2; j2++) {
                float2 v;
                v.x = accO[i][j2][2*rh  ] * inv;
                v.y = accO[i][j2][2*rh+1] * inv;
                *(float2*)&Yg[base + (long)(qb*128 + row)*DMODEL + wx*16 + 8*j2 + 2*t] = v;
            }
        }
    }
}

// ===========================================================================
// LayerNorm / pos-add
// ===========================================================================
__global__ void add_ln_k(const float* __restrict__ X, const float* __restrict__ Y,
                         const float* __restrict__ g, const float* __restrict__ b,
                         float* __restrict__ O)
{
    const long row = blockIdx.x;
    const float* x = X + row * DMODEL;
    const float* y = Y + row * DMODEL;
    float* o = O + row * DMODEL;
    const int t = threadIdx.x;
    __shared__ float sm[4];

    float v[4];
    float s = 0.f;
    #pragma unroll
    for (int i = 0; i < 4; i++) {
        int j = t + i*128;
        v[i] = x[j] + y[j];
        s += v[i];
    }
    #pragma unroll
    for (int o2 = 16; o2 > 0; o2 >>= 1) s += __shfl_xor_sync(0xffffffffu, s, o2);
    if ((t & 31) == 0) sm[t >> 5] = s;
    __syncthreads();
    const float mu = (sm[0]+sm[1]+sm[2]+sm[3]) * (1.f/DMODEL);
    __syncthreads();
    float var = 0.f;
    #pragma unroll
    for (int i = 0; i < 4; i++) { float d = v[i]-mu; var += d*d; }
    #pragma unroll
    for (int o2 = 16; o2 > 0; o2 >>= 1) var += __shfl_xor_sync(0xffffffffu, var, o2);
    if ((t & 31) == 0) sm[t >> 5] = var;
    __syncthreads();
    const float rs = rsqrtf((sm[0]+sm[1]+sm[2]+sm[3]) * (1.f/DMODEL) + 1e-5f);
    #pragma unroll
    for (int i = 0; i < 4; i++) {
        int j = t + i*128;
        o[j] = (v[i]-mu)*rs*g[j] + b[j];
    }
}

__global__ void addpos_k(const float* __restrict__ x, const float* __restrict__ pos,
                         float* __restrict__ o)
{
    long idx = (long)blockIdx.x * 256 + threadIdx.x;
    long sd  = idx % ((long)SEQ * DMODEL);
    o[idx] = x[idx] + pos[sd];
}

// ===========================================================================
// Host-side launch helpers
// ===========================================================================
static const int SMEM_D = 2*(128*20 + 128*20)*4;   // 40960 B

static void dense32(const float* A, const float* Bt, const float* bias, float* C,
                    int M, int N, int K, long sBb, long sCb, long sbz, int nz)
{
    dim3 grid(N/128, M/128, nz);
    gemm_mma_k<0,true,false><<<grid,256,SMEM_D>>>(A,Bt,bias,C,K, K,K,N, sBb,sCb,sbz);
}
static void dense16(const float* A, const float* Bt, const float* bias, float* C,
                    int M, int N, int K, bool relu)
{
    dim3 grid(N/128, M/128, 1);
    if (relu)
        gemm_mma_k<1,true,true ><<<grid,256,SMEM_D>>>(A,Bt,bias,C,K, K,K,N, 0,0,0);
    else
        gemm_mma_k<1,true,false><<<grid,256,SMEM_D>>>(A,Bt,bias,C,K, K,K,N, 0,0,0);
}

extern "C" void kernel_launch(void* const* d_in, const int* in_sizes, int n_in,
                              void* d_out, int out_size)
{
    const float* kv   = (const float*)d_in[0];
    const float* xin  = (const float*)d_in[1];
    const float* pos  = (const float*)d_in[2];
    const float* sqW  = (const float*)d_in[3];  const float* sqb = (const float*)d_in[4];
    const float* skW  = (const float*)d_in[5];  const float* skb = (const float*)d_in[6];
    const float* svW  = (const float*)d_in[7];  const float* svb = (const float*)d_in[8];
    const float* soW  = (const float*)d_in[9];  const float* sob = (const float*)d_in[10];
    const float* cqW  = (const float*)d_in[11]; const float* cqb = (const float*)d_in[12];
    const float* ckW  = (const float*)d_in[13]; const float* ckb = (const float*)d_in[14];
    const float* cvW  = (const float*)d_in[15]; const float* cvb = (const float*)d_in[16];
    const float* coW  = (const float*)d_in[17]; const float* cob = (const float*)d_in[18];
    const float* f1W  = (const float*)d_in[19]; const float* f1b = (const float*)d_in[20];
    const float* f2W  = (const float*)d_in[21]; const float* f2b = (const float*)d_in[22];
    const float* g1   = (const float*)d_in[23]; const float* b1  = (const float*)d_in[24];
    const float* g2   = (const float*)d_in[25]; const float* b2  = (const float*)d_in[26];
    const float* g3   = (const float*)d_in[27]; const float* b3  = (const float*)d_in[28];
    float* out = (float*)d_out;

    cudaFuncSetAttribute(gemm_mma_k<0,true,false>, cudaFuncAttributeMaxDynamicSharedMemorySize, SMEM_D);
    cudaFuncSetAttribute(gemm_mma_k<1,true,false>, cudaFuncAttributeMaxDynamicSharedMemorySize, SMEM_D);
    cudaFuncSetAttribute(gemm_mma_k<1,true,true >, cudaFuncAttributeMaxDynamicSharedMemorySize, SMEM_D);
    cudaFuncSetAttribute(flash_k<true >, cudaFuncAttributeMaxDynamicSharedMemorySize, FLASH_SMEM);
    cudaFuncSetAttribute(flash_k<false>, cudaFuncAttributeMaxDynamicSharedMemorySize, FLASH_SMEM);

    float *px,*pqkv,*py,*pt,*pf,*pwt,*pbias;
    cudaGetSymbolAddress((void**)&px, g_x);
    cudaGetSymbolAddress((void**)&pqkv, g_qkv);
    cudaGetSymbolAddress((void**)&py, g_y);
    cudaGetSymbolAddress((void**)&pt, g_t);
    cudaGetSymbolAddress((void**)&pf, g_f);
    cudaGetSymbolAddress((void**)&pwt, g_wt);
    cudaGetSymbolAddress((void**)&pbias, g_bias);

    const long DD = (long)DMODEL*DMODEL;
    const long DF = (long)DMODEL*FDIM;
    const long MD = (long)MROWS*DMODEL;

    float* pq = pqkv;
    float* pk = pqkv + MD;
    float* pv = pqkv + 2*MD;

    // Family order in g_wt: sq sk sv so cq ck cv co (each 12*DD), then f1T, f2T
    float* sqT = pwt;            float* skT = pwt + 12*DD;
    float* svT = pwt + 24*DD;    float* soT = pwt + 36*DD;
    float* cqT = pwt + 48*DD;    float* ckT = pwt + 60*DD;
    float* cvT = pwt + 72*DD;    float* coT = pwt + 84*DD;
    float* f1T = pwt + 96*DD;            // [L][FDIM][DMODEL]
    float* f2T = f1T + 12*DF;            // [L][DMODEL][FDIM]

    // 5 setup launches (so ncu -s 5 lands on the first real GEMM)
    {
        dim3 blk(32, 8);
        transpose8_k<<<dim3(16,16,8*NLAYERS), blk>>>(sqW, skW, svW, soW,
                                                     cqW, ckW, cvW, coW, pwt);
        transpose_k<<<dim3(64,16,NLAYERS), blk>>>(f1W, f1T, DMODEL, FDIM);
        transpose_k<<<dim3(16,64,NLAYERS), blk>>>(f2W, f2T, FDIM, DMODEL);
        packbias_k<<<(4*NLAYERS*DMODEL)/256, 256>>>(sqb, skb, ckb, cvb, pbias);
    }

    addpos_k<<<(MROWS*DMODEL)/256, 256>>>(xin, pos, px);

    const long LB = (long)NLAYERS*DMODEL;
    const dim3 fgrid(SEQ/128, BATCH*NHEADS);

    for (int l = 0; l < NLAYERS; l++) {
        // ---- self-attention (causal) ----
        dense32(px, sqT + l*DD, pbias + l*DMODEL, pq,
                MROWS, DMODEL, DMODEL, 12*DD, MD, LB, 2);      // Q and K batched
        dense16(px, svT + l*DD, svb + l*DMODEL, pv, MROWS, DMODEL, DMODEL, false);
        flash_k<true ><<<fgrid, 256, FLASH_SMEM>>>(pq, pk, pv, py);
        dense16(py, soT + l*DD, sob + l*DMODEL, pt, MROWS, DMODEL, DMODEL, false);
        add_ln_k<<<MROWS, 128>>>(px, pt, g1 + l*DMODEL, b1 + l*DMODEL, px);

        // ---- cross-attention ----
        dense32(px, cqT + l*DD, cqb + l*DMODEL, pq,
                MROWS, DMODEL, DMODEL, 0, 0, 0, 1);
        dense32(kv, ckT + l*DD, pbias + 2*LB + l*DMODEL, pk,
                MROWS, DMODEL, DMODEL, 12*DD, MD, LB, 2);      // K and V batched
        flash_k<false><<<fgrid, 256, FLASH_SMEM>>>(pq, pk, pv, py);
        dense16(py, coT + l*DD, cob + l*DMODEL, pt, MROWS, DMODEL, DMODEL, false);
        add_ln_k<<<MROWS, 128>>>(px, pt, g2 + l*DMODEL, b2 + l*DMODEL, px);

        // ---- FFN ----
        dense16(px, f1T + l*DF, f1b + l*FDIM, pf, MROWS, FDIM, DMODEL, true);
        dense16(pf, f2T + l*DF, f2b + l*DMODEL, pt, MROWS, DMODEL, FDIM, false);
        add_ln_k<<<MROWS, 128>>>(px, pt, g3 + l*DMODEL, b3 + l*DMODEL,
                                 (l == NLAYERS-1) ? out : px);
    }
}

// round 11
// speedup vs baseline: 1.9941x; 1.0677x over previous
#include <cuda_runtime.h>
#include <cstdint>

// Problem constants
#define NLAYERS 12
#define BATCH   4
#define SEQ     1024
#define DMODEL  512
#define NHEADS  8
#define DHEAD   64
#define FDIM    2048
#define MROWS   (BATCH*SEQ)   // 4096

// ===========================================================================
// sm_80-level PTX helpers
// ===========================================================================
#define CP_ASYNC16(dst, src) \
    asm volatile("cp.async.cg.shared.global [%0], [%1], 16;" :: "r"(dst), "l"(src))
#define CP_COMMIT() asm volatile("cp.async.commit_group;" ::: "memory")
#define CP_WAIT0()  asm volatile("cp.async.wait_group 0;" ::: "memory")
#define CP_WAIT1()  asm volatile("cp.async.wait_group 1;" ::: "memory")

__device__ __forceinline__ void tf32_split(float x, uint32_t& hi, uint32_t& lo) {
    uint32_t h;
    asm("cvt.rna.tf32.f32 %0, %1;" : "=r"(h) : "f"(x));
    float r = x - __uint_as_float(h);
    uint32_t l;
    asm("cvt.rna.tf32.f32 %0, %1;" : "=r"(l) : "f"(r));
    hi = h; lo = l;
}

// Split two fp32 (k-adjacent pair) into packed bf16x2 hi and lo parts.
// Lower 16 bits hold x0 (even k), upper hold x1 (odd k).
__device__ __forceinline__ void bf16_split2(float x0, float x1,
                                            uint32_t& hi, uint32_t& lo) {
    uint32_t h;
    asm("cvt.rn.bf16x2.f32 %0, %1, %2;" : "=r"(h) : "f"(x1), "f"(x0));
    float h0 = __uint_as_float(h << 16);
    float h1 = __uint_as_float(h & 0xffff0000u);
    float r0 = x0 - h0, r1 = x1 - h1;
    uint32_t l;
    asm("cvt.rn.bf16x2.f32 %0, %1, %2;" : "=r"(l) : "f"(r1), "f"(r0));
    hi = h; lo = l;
}

__device__ __forceinline__ void mma8(float* c, const uint32_t* a, const uint32_t* b) {
    asm volatile(
        "mma.sync.aligned.m16n8k8.row.col.f32.tf32.tf32.f32 "
        "{%0,%1,%2,%3}, {%4,%5,%6,%7}, {%8,%9}, {%0,%1,%2,%3};"
        : "+f"(c[0]), "+f"(c[1]), "+f"(c[2]), "+f"(c[3])
        : "r"(a[0]), "r"(a[1]), "r"(a[2]), "r"(a[3]), "r"(b[0]), "r"(b[1]));
}

__device__ __forceinline__ void mma16(float* c, const uint32_t* a, const uint32_t* b) {
    asm volatile(
        "mma.sync.aligned.m16n8k16.row.col.f32.bf16.bf16.f32 "
        "{%0,%1,%2,%3}, {%4,%5,%6,%7}, {%8,%9}, {%0,%1,%2,%3};"
        : "+f"(c[0]), "+f"(c[1]), "+f"(c[2]), "+f"(c[3])
        : "r"(a[0]), "r"(a[1]), "r"(a[2]), "r"(a[3]), "r"(b[0]), "r"(b[1]));
}

// ===========================================================================
// Scratch (static device globals; no allocation anywhere)
// ===========================================================================
__device__ float g_x[MROWS*DMODEL];
__device__ float g_qkv[3L*MROWS*DMODEL];     // q, k, v slabs
__device__ float g_y[MROWS*DMODEL];
__device__ float g_t[MROWS*DMODEL];
__device__ float g_f[MROWS*FDIM];
__device__ float g_wt[48L*DMODEL*DMODEL];    // tf32 fams transposed: sq sk cq ck
// bf16 pre-split weights, packed bf16x2 along K: [fam][layer][N][K/2]
// sv@0, so@12*131072, cv@24*.., co@36*.., f1@48*131072=6291456, f2@12582912
__device__ uint32_t g_whi[18874368];
__device__ uint32_t g_wlo[18874368];
__device__ float g_bias[4L*NLAYERS*DMODEL];  // packed biases (slots 0,1 used: sq, sk)

// ===========================================================================
// Setup kernels
// ===========================================================================
// Transpose 4 DxD tf32-path families in one launch (z = 4*12)
__global__ void transpose4_k(const float* __restrict__ s0, const float* __restrict__ s1,
                             const float* __restrict__ s2, const float* __restrict__ s3,
                             float* __restrict__ dstBase)
{
    __shared__ float tt[32][33];
    const int z = blockIdx.z;
    const int f = z / NLAYERS, ly = z % NLAYERS;
    const float* S = (f == 0) ? s0 : (f == 1) ? s1 : (f == 2) ? s2 : s3;
    const long DD = (long)DMODEL*DMODEL;
    S += (long)ly * DD;
    float* D = dstBase + (long)f*NLAYERS*DD + (long)ly*DD;

    const int c0 = blockIdx.x * 32, r0 = blockIdx.y * 32;
    const int tx = threadIdx.x, ty = threadIdx.y;
    #pragma unroll
    for (int i = 0; i < 32; i += 8)
        tt[ty + i][tx] = S[(long)(r0 + ty + i)*DMODEL + c0 + tx];
    __syncthreads();
    #pragma unroll
    for (int i = 0; i < 32; i += 8)
        D[(long)(c0 + ty + i)*DMODEL + r0 + tx] = tt[tx][ty + i];
}

// Transpose + bf16-split 4 DxD bf16-path families (z = 4*12).
// Input W[K][N]; output hi/lo packed [N][K/2].
__global__ void tsplit4_k(const float* __restrict__ s0, const float* __restrict__ s1,
                          const float* __restrict__ s2, const float* __restrict__ s3,
                          uint32_t* __restrict__ dhi, uint32_t* __restrict__ dlo)
{
    __shared__ float tt[32][33];
    const int z = blockIdx.z;
    const int f = z / NLAYERS, ly = z % NLAYERS;
    const float* S = (f == 0) ? s0 : (f == 1) ? s1 : (f == 2) ? s2 : s3;
    S += (long)ly * DMODEL*DMODEL;
    const long obase = (long)f*NLAYERS*DMODEL*(DMODEL/2) + (long)ly*DMODEL*(DMODEL/2);
    uint32_t* DH = dhi + obase;
    uint32_t* DL = dlo + obase;

    const int k0 = blockIdx.y * 32, n0 = blockIdx.x * 32;
    const int tx = threadIdx.x, ty = threadIdx.y;
    #pragma unroll
    for (int i = 0; i < 32; i += 8)
        tt[ty + i][tx] = S[(long)(k0 + ty + i)*DMODEL + n0 + tx];   // tt[k][n]
    __syncthreads();
    const int base = ty*32 + tx;
    #pragma unroll
    for (int q = 0; q < 2; q++) {
        const int o = base + q*256;
        const int nl = o >> 4, kkl = o & 15;
        uint32_t h, l;
        bf16_split2(tt[2*kkl][nl], tt[2*kkl + 1][nl], h, l);
        DH[(long)(n0 + nl)*(DMODEL/2) + (k0 >> 1) + kkl] = h;
        DL[(long)(n0 + nl)*(DMODEL/2) + (k0 >> 1) + kkl] = l;
    }
}

// Generic transpose+split (for f1: R=512,C=2048; f2: R=2048,C=512), z = layers
__global__ void tsplit_k(const float* __restrict__ S, uint32_t* __restrict__ DH,
                         uint32_t* __restrict__ DL, int R, int C)
{
    __shared__ float tt[32][33];
    const long ly = blockIdx.z;
    S  += ly * (long)R * C;
    DH += ly * (long)C * (R/2);
    DL += ly * (long)C * (R/2);

    const int k0 = blockIdx.y * 32, n0 = blockIdx.x * 32;
    const int tx = threadIdx.x, ty = threadIdx.y;
    #pragma unroll
    for (int i = 0; i < 32; i += 8)
        tt[ty + i][tx] = S[(long)(k0 + ty + i)*C + n0 + tx];
    __syncthreads();
    const int base = ty*32 + tx;
    #pragma unroll
    for (int q = 0; q < 2; q++) {
        const int o = base + q*256;
        const int nl = o >> 4, kkl = o & 15;
        uint32_t h, l;
        bf16_split2(tt[2*kkl][nl], tt[2*kkl + 1][nl], h, l);
        DH[(long)(n0 + nl)*(R/2) + (k0 >> 1) + kkl] = h;
        DL[(long)(n0 + nl)*(R/2) + (k0 >> 1) + kkl] = l;
    }
}

__global__ void packbias_k(const float* __restrict__ a0, const float* __restrict__ a1,
                           const float* __restrict__ a2, const float* __restrict__ a3,
                           float* __restrict__ dst)
{
    const int i = blockIdx.x*256 + threadIdx.x;
    const int f = i / (NLAYERS*DMODEL), r = i % (NLAYERS*DMODEL);
    const float* s = (f == 0) ? a0 : (f == 1) ? a1 : (f == 2) ? a2 : a3;
    dst[i] = s[r];
}

// ===========================================================================
// tf32 GEMM — VALIDATED (unchanged). TB layout (Bt[N][K] transposed weights).
// ===========================================================================
template<bool BIAS>
__global__ __launch_bounds__(256, 1) void gemm_tf32_k(
    const float* __restrict__ A, const float* __restrict__ Bm,
    const float* __restrict__ bias, float* __restrict__ C,
    int K, int lda, int ldb, int ldc,
    long sBb, long sCb, long sbz)
{
    constexpr int AS   = 20;
    constexpr int BS   = 20;
    constexpr int ABUF = 128*AS;
    constexpr int BBUF = 128*BS;

    const int row0 = blockIdx.y * 128;
    const int col0 = blockIdx.x * 128;
    const int zb = blockIdx.z;
    Bm += (long)zb*sBb;
    C  += (long)zb*sCb;
    if (BIAS) bias += (long)zb*sbz;

    extern __shared__ float smf[];
    float* Asm = smf;
    float* Bsm = smf + 2*ABUF;

    const int tid  = threadIdx.x;
    const int wid  = tid >> 5;
    const int lane = tid & 31;
    const int g = lane >> 2, t = lane & 3;
    const int wm = (wid >> 2) * 64;
    const int wn = (wid & 3) * 32;

    const int ns = K >> 4;

    auto loadA = [&](int s) {
        float* dst = Asm + (s & 1) * ABUF;
        const int r  = tid >> 1;
        const int kc = (tid & 1) << 3;
        uint32_t d = (uint32_t)__cvta_generic_to_shared(dst + r*AS + kc);
        CP_ASYNC16(d, A + (long)(row0 + r)*lda + (s << 4) + kc);
        uint32_t d2 = (uint32_t)__cvta_generic_to_shared(dst + r*AS + kc + 4);
        CP_ASYNC16(d2, A + (long)(row0 + r)*lda + (s << 4) + kc + 4);
    };
    auto loadB = [&](int s) {
        float* dst = Bsm + (s & 1) * BBUF;
        const int r  = tid >> 1;
        const int kc = (tid & 1) << 3;
        uint32_t d = (uint32_t)__cvta_generic_to_shared(dst + r*BS + kc);
        CP_ASYNC16(d, Bm + (long)(col0 + r)*ldb + (s << 4) + kc);
        uint32_t d2 = (uint32_t)__cvta_generic_to_shared(dst + r*BS + kc + 4);
        CP_ASYNC16(d2, Bm + (long)(col0 + r)*ldb + (s << 4) + kc + 4);
    };

    float acc[4][4][4] = {};

    loadA(0); loadB(0); CP_COMMIT();

    for (int s = 0; s < ns; s++) {
        if (s + 1 < ns) { loadA(s+1); loadB(s+1); CP_COMMIT(); CP_WAIT1(); }
        else            { CP_WAIT0(); }
        __syncthreads();

        const float* a = Asm + (s & 1) * ABUF;
        const float* b = Bsm + (s & 1) * BBUF;

        #pragma unroll
        for (int kk = 0; kk < 16; kk += 8) {
            uint32_t ahi[4][4], alo[4][4];
            #pragma unroll
            for (int i = 0; i < 4; i++) {
                const int m0 = wm + 16*i + g;
                tf32_split(a[(m0    )*AS + kk + t    ], ahi[i][0], alo[i][0]);
                tf32_split(a[(m0 + 8)*AS + kk + t    ], ahi[i][1], alo[i][1]);
                tf32_split(a[(m0    )*AS + kk + t + 4], ahi[i][2], alo[i][2]);
                tf32_split(a[(m0 + 8)*AS + kk + t + 4], ahi[i][3], alo[i][3]);
            }
            #pragma unroll
            for (int j = 0; j < 4; j++) {
                const int n0 = wn + 8*j + g;
                uint32_t bhi[2], blo[2];
                tf32_split(b[n0*BS + kk + t    ], bhi[0], blo[0]);
                tf32_split(b[n0*BS + kk + t + 4], bhi[1], blo[1]);
                #pragma unroll
                for (int i = 0; i < 4; i++) {
                    mma8(acc[i][j], ahi[i], bhi);
                    mma8(acc[i][j], ahi[i], blo);
                    mma8(acc[i][j], alo[i], bhi);
                }
            }
        }
        __syncthreads();
    }

    #pragma unroll
    for (int j = 0; j < 4; j++) {
        const int cb = col0 + wn + 8*j + 2*t;
        float bx = 0.f, by = 0.f;
        if (BIAS) { bx = bias[cb]; by = bias[cb + 1]; }
        #pragma unroll
        for (int i = 0; i < 4; i++) {
            const int r = row0 + wm + 16*i + g;
            float2 v0, v1;
            v0.x = acc[i][j][0] + bx; v0.y = acc[i][j][1] + by;
            v1.x = acc[i][j][2] + bx; v1.y = acc[i][j][3] + by;
            *(float2*)&C[(long)r*ldc + cb]       = v0;
            *(float2*)&C[(long)(r + 8)*ldc + cb] = v1;
        }
    }
}

// ===========================================================================
// bf16 GEMM v2 — B from pre-split packed weights, A split staged in SMEM.
// SMEM floats: A 2x2560 | Ahi 1536 | Alo 1536 | Bhi 2x1536 | Blo 2x1536
//            = 14336 floats = 57344 B
// ===========================================================================
#define SMEM_B16 57344

template<bool BIAS, bool RELU>
__global__ __launch_bounds__(256, 1) void gemm_bf16_k(
    const float* __restrict__ A, const uint32_t* __restrict__ Whi,
    const uint32_t* __restrict__ Wlo, const float* __restrict__ bias,
    float* __restrict__ C, int K, int lda, int ldw, int ldc)
{
    constexpr int AS = 20;
    constexpr int WS = 12;

    const int row0 = blockIdx.y * 128;
    const int col0 = blockIdx.x * 128;

    extern __shared__ float smf[];
    float*    Asm = smf;                          // 2 * 2560
    uint32_t* AH  = (uint32_t*)(smf + 5120);      // 1536
    uint32_t* AL  = (uint32_t*)(smf + 6656);      // 1536
    uint32_t* BH  = (uint32_t*)(smf + 8192);      // 2 * 1536
    uint32_t* BL  = (uint32_t*)(smf + 11264);     // 2 * 1536

    const int tid  = threadIdx.x;
    const int wid  = tid >> 5;
    const int lane = tid & 31;
    const int g = lane >> 2, t = lane & 3;
    const int wm = (wid >> 2) * 64;
    const int wn = (wid & 3) * 32;

    const int ns = K >> 4;

    auto loadA = [&](int s) {
        float* dst = Asm + (s & 1) * 2560;
        const int r  = tid >> 1;
        const int kc = (tid & 1) << 3;
        uint32_t d = (uint32_t)__cvta_generic_to_shared(dst + r*AS + kc);
        CP_ASYNC16(d, A + (long)(row0 + r)*lda + (s << 4) + kc);
        uint32_t d2 = (uint32_t)__cvta_generic_to_shared(dst + r*AS + kc + 4);
        CP_ASYNC16(d2, A + (long)(row0 + r)*lda + (s << 4) + kc + 4);
    };
    auto loadB = [&](int s) {
        uint32_t* dh = BH + (s & 1) * 1536;
        uint32_t* dl = BL + (s & 1) * 1536;
        const int r = tid >> 1, half = (tid & 1) << 2;
        uint32_t d = (uint32_t)__cvta_generic_to_shared(dh + r*WS + half);
        CP_ASYNC16(d, Whi + (long)(col0 + r)*ldw + (s << 3) + half);
        uint32_t d2 = (uint32_t)__cvta_generic_to_shared(dl + r*WS + half);
        CP_ASYNC16(d2, Wlo + (long)(col0 + r)*ldw + (s << 3) + half);
    };

    float acc[4][4][4] = {};

    loadA(0); loadB(0); CP_COMMIT();

    for (int s = 0; s < ns; s++) {
        if (s + 1 < ns) { loadA(s+1); loadB(s+1); CP_COMMIT(); CP_WAIT1(); }
        else            { CP_WAIT0(); }
        __syncthreads();

        // --- stage A split: 128x16 fp32 -> packed bf16x2 hi/lo [128][8] ---
        {
            const float* a = Asm + (s & 1) * 2560;
            #pragma unroll
            for (int p2 = 0; p2 < 4; p2++) {
                const int p = tid + (p2 << 8);
                const int r = p >> 3, c2 = p & 7;
                float2 x = *(const float2*)&a[r*AS + 2*c2];
                uint32_t h, l;
                bf16_split2(x.x, x.y, h, l);
                AH[r*WS + c2] = h;
                AL[r*WS + c2] = l;
            }
        }
        __syncthreads();

        const uint32_t* bh = BH + (s & 1) * 1536;
        const uint32_t* bl = BL + (s & 1) * 1536;

        uint32_t ahi[4][4], alo[4][4];
        #pragma unroll
        for (int i = 0; i < 4; i++) {
            #pragma unroll
            for (int rr = 0; rr < 4; rr++) {
                const int r  = wm + 16*i + g + 8*(rr & 1);
                const int cc = t + 4*(rr >> 1);
                ahi[i][rr] = AH[r*WS + cc];
                alo[i][rr] = AL[r*WS + cc];
            }
        }
        #pragma unroll
        for (int j = 0; j < 4; j++) {
            const int n0 = wn + 8*j + g;
            uint32_t bhi[2], blo[2];
            bhi[0] = bh[n0*WS + t];     bhi[1] = bh[n0*WS + t + 4];
            blo[0] = bl[n0*WS + t];     blo[1] = bl[n0*WS + t + 4];
            #pragma unroll
            for (int i = 0; i < 4; i++) {
                mma16(acc[i][j], ahi[i], bhi);
                mma16(acc[i][j], ahi[i], blo);
                mma16(acc[i][j], alo[i], bhi);
            }
        }
        __syncthreads();
    }

    #pragma unroll
    for (int j = 0; j < 4; j++) {
        const int cb = col0 + wn + 8*j + 2*t;
        float bx = 0.f, by = 0.f;
        if (BIAS) { bx = bias[cb]; by = bias[cb + 1]; }
        #pragma unroll
        for (int i = 0; i < 4; i++) {
            const int r = row0 + wm + 16*i + g;
            float2 v0, v1;
            v0.x = acc[i][j][0] + bx; v0.y = acc[i][j][1] + by;
            v1.x = acc[i][j][2] + bx; v1.y = acc[i][j][3] + by;
            if (RELU) {
                v0.x = fmaxf(v0.x, 0.f); v0.y = fmaxf(v0.y, 0.f);
                v1.x = fmaxf(v1.x, 0.f); v1.y = fmaxf(v1.y, 0.f);
            }
            *(float2*)&C[(long)r*ldc + cb]       = v0;
            *(float2*)&C[(long)(r + 8)*ldc + cb] = v1;
        }
    }
}

// ===========================================================================
// Flash attention v3: Q pre-split (tf32 hi/lo) once; K,V single-buffered.
// Softmax/P/PV logic identical to the validated round-9 kernel.
// SMEM floats: QH 128x68 | QL 128x68 | K 128x68 | V 128x68 |
//              P 128x66 uint2 | rm 512 | rs 512  = 52736 floats = 210944 B
// ===========================================================================
#define TSF 68
#define PST 66
#define FLASH_SMEM 210944

template<bool CAUSAL>
__global__ __launch_bounds__(256, 1) void flash_k(
    const float* __restrict__ Qg, const float* __restrict__ Kg,
    const float* __restrict__ Vg, float* __restrict__ Yg)
{
    extern __shared__ float sm[];
    constexpr int QHOFF = 0;
    constexpr int QLOFF = 128*TSF;            // 8704
    constexpr int KOFF  = 2*128*TSF;          // 17408
    constexpr int VOFF  = 3*128*TSF;          // 26112
    constexpr int POFF  = 4*128*TSF;          // 34816 (floats)
    constexpr int RMOFF = POFF + 128*PST*2;   // 51712
    constexpr int RSOFF = RMOFF + 512;        // 52224

    const int qb = blockIdx.x;
    const int bh = blockIdx.y;
    const long base = ((long)(bh >> 3)*SEQ)*DMODEL + (bh & 7)*DHEAD;
    const float* Kp = Kg + base;
    const float* Vp = Vg + base;

    const int tid = threadIdx.x;
    const int wid = tid >> 5, lane = tid & 31;
    const int g = lane >> 2, t = lane & 3;
    const int wy = wid >> 2, wx = wid & 3;    // 2 x 4 warp grid

    const int nb = CAUSAL ? (qb + 1) : (SEQ/128);

    auto load_tile = [&](int off, const float* src) {
        #pragma unroll
        for (int it = 0; it < 8; it++) {
            const int idx = tid + (it << 8);
            const int r = idx >> 4, c = (idx & 15) << 2;
            uint32_t d = (uint32_t)__cvta_generic_to_shared(sm + off + r*TSF + c);
            CP_ASYNC16(d, src + (long)r*DMODEL + c);
        }
    };

    // Load Q into the K buffer, then split once into QH/QL.
    load_tile(KOFF, Qg + base + (long)qb*128*DMODEL);
    CP_COMMIT(); CP_WAIT0();
    __syncthreads();
    {
        uint32_t* QH = (uint32_t*)(sm + QHOFF);
        uint32_t* QL = (uint32_t*)(sm + QLOFF);
        const float* qsrc = sm + KOFF;
        #pragma unroll
        for (int i2 = 0; i2 < 32; i2++) {
            const int p = tid + (i2 << 8);
            const int r = p >> 6, c = p & 63;
            uint32_t h, l;
            tf32_split(qsrc[r*TSF + c], h, l);
            QH[r*TSF + c] = h;
            QL[r*TSF + c] = l;
        }
    }
    __syncthreads();

    const uint32_t* QH = (const uint32_t*)(sm + QHOFF);
    const uint32_t* QL = (const uint32_t*)(sm + QLOFF);

    float m[8], l[8];
    #pragma unroll
    for (int s = 0; s < 8; s++) { m[s] = -1e30f; l[s] = 0.f; }
    float accO[4][2][4] = {};

    uint2* Pp = (uint2*)(sm + POFF);

    for (int n = 0; n < nb; n++) {
        __syncthreads();                        // prior consumers of K/V done
        load_tile(KOFF, Kp + (long)n*128*DMODEL);
        load_tile(VOFF, Vp + (long)n*128*DMODEL);
        CP_COMMIT(); CP_WAIT0();
        __syncthreads();

        // ---- S = Q @ K^T (3xTF32; Q fragments pre-split) ----
        float accS[4][4][4] = {};
        #pragma unroll
        for (int kk = 0; kk < 64; kk += 8) {
            uint32_t ahi[4][4], alo[4][4];
            #pragma unroll
            for (int i = 0; i < 4; i++) {
                const int mb = wy*64 + 16*i + g;
                ahi[i][0] = QH[(mb    )*TSF + kk + t    ];
                ahi[i][1] = QH[(mb + 8)*TSF + kk + t    ];
                ahi[i][2] = QH[(mb    )*TSF + kk + t + 4];
                ahi[i][3] = QH[(mb + 8)*TSF + kk + t + 4];
                alo[i][0] = QL[(mb    )*TSF + kk + t    ];
                alo[i][1] = QL[(mb + 8)*TSF + kk + t    ];
                alo[i][2] = QL[(mb    )*TSF + kk + t + 4];
                alo[i][3] = QL[(mb + 8)*TSF + kk + t + 4];
            }
            #pragma unroll
            for (int j = 0; j < 4; j++) {
                const int n0 = wx*32 + 8*j + g;
                uint32_t bhi[2], blo[2];
                tf32_split(sm[KOFF + n0*TSF + kk + t    ], bhi[0], blo[0]);
                tf32_split(sm[KOFF + n0*TSF + kk + t + 4], bhi[1], blo[1]);
                #pragma unroll
                for (int i = 0; i < 4; i++) {
                    mma8(accS[i][j], ahi[i], bhi);
                    mma8(accS[i][j], ahi[i], blo);
                    mma8(accS[i][j], alo[i], bhi);
                }
            }
        }

        // ---- causal mask on diagonal block ----
        if (CAUSAL && n == qb) {
            #pragma unroll
            for (int i = 0; i < 4; i++) {
                const int r0 = wy*64 + 16*i + g;
                #pragma unroll
                for (int j = 0; j < 4; j++) {
                    const int c0 = wx*32 + 8*j + 2*t;
                    if (c0     > r0    ) accS[i][j][0] = -1e30f;
                    if (c0 + 1 > r0    ) accS[i][j][1] = -1e30f;
                    if (c0     > r0 + 8) accS[i][j][2] = -1e30f;
                    if (c0 + 1 > r0 + 8) accS[i][j][3] = -1e30f;
                }
            }
        }

        // ---- per-warp partial row max -> rm ----
        #pragma unroll
        for (int i = 0; i < 4; i++) {
            #pragma unroll
            for (int rh = 0; rh < 2; rh++) {
                float pm = -1e30f;
                #pragma unroll
                for (int j = 0; j < 4; j++)
                    pm = fmaxf(pm, fmaxf(accS[i][j][2*rh], accS[i][j][2*rh+1]));
                pm = fmaxf(pm, __shfl_xor_sync(0xffffffffu, pm, 1));
                pm = fmaxf(pm, __shfl_xor_sync(0xffffffffu, pm, 2));
                if (t == 0) sm[RMOFF + (wy*64 + 16*i + g + 8*rh)*4 + wx] = pm;
            }
        }
        __syncthreads();

        // ---- online softmax: rescale O/l, pack P (bf16 hi/lo), partial sums ----
        #pragma unroll
        for (int i = 0; i < 4; i++) {
            #pragma unroll
            for (int rh = 0; rh < 2; rh++) {
                const int s = 2*i + rh;
                const int row = wy*64 + 16*i + g + 8*rh;
                const float* rm = sm + RMOFF + row*4;
                float bm = fmaxf(fmaxf(rm[0], rm[1]), fmaxf(rm[2], rm[3]));
                float mnew = fmaxf(m[s], bm);
                float alpha = __expf((m[s] - mnew) * 0.125f);
                m[s] = mnew;
                l[s] *= alpha;
                #pragma unroll
                for (int j2 = 0; j2 < 2; j2++) {
                    accO[i][j2][2*rh  ] *= alpha;
                    accO[i][j2][2*rh+1] *= alpha;
                }
                float ps = 0.f;
                #pragma unroll
                for (int j = 0; j < 4; j++) {
                    float e0 = __expf((accS[i][j][2*rh  ] - mnew) * 0.125f);
                    float e1 = __expf((accS[i][j][2*rh+1] - mnew) * 0.125f);
                    ps += e0 + e1;
                    uint32_t hi, lo;
                    bf16_split2(e0, e1, hi, lo);
                    Pp[row*PST + wx*16 + 4*j + t] = make_uint2(hi, lo);
                }
                ps += __shfl_xor_sync(0xffffffffu, ps, 1);
                ps += __shfl_xor_sync(0xffffffffu, ps, 2);
                if (t == 0) sm[RSOFF + row*4 + wx] = ps;
            }
        }
        __syncthreads();

        #pragma unroll
        for (int i = 0; i < 4; i++)
            #pragma unroll
            for (int rh = 0; rh < 2; rh++) {
                const int row = wy*64 + 16*i + g + 8*rh;
                const float* rs = sm + RSOFF + row*4;
                l[2*i + rh] += rs[0] + rs[1] + rs[2] + rs[3];
            }

        // ---- O += P @ V (3-term bf16) ----
        #pragma unroll
        for (int kt = 0; kt < 8; kt++) {
            uint32_t pahi[4][4], palo[4][4];
            #pragma unroll
            for (int i = 0; i < 4; i++) {
                #pragma unroll
                for (int rr = 0; rr < 4; rr++) {
                    const int r  = wy*64 + 16*i + g + 8*(rr & 1);
                    const int kp = kt*8 + t + 4*(rr >> 1);
                    uint2 hl = Pp[r*PST + kp];
                    pahi[i][rr] = hl.x; palo[i][rr] = hl.y;
                }
            }
            #pragma unroll
            for (int j2 = 0; j2 < 2; j2++) {
                const int n0 = wx*16 + 8*j2 + g;
                uint32_t vh[2], vl[2];
                #pragma unroll
                for (int rr = 0; rr < 2; rr++) {
                    const int kc = kt*16 + 2*t + 8*rr;
                    bf16_split2(sm[VOFF + kc*TSF + n0], sm[VOFF + (kc+1)*TSF + n0],
                                vh[rr], vl[rr]);
                }
                #pragma unroll
                for (int i = 0; i < 4; i++) {
                    mma16(accO[i][j2], pahi[i], vh);
                    mma16(accO[i][j2], pahi[i], vl);
                    mma16(accO[i][j2], palo[i], vh);
                }
            }
        }
    }

    // ---- normalize and write O ----
    #pragma unroll
    for (int i = 0; i < 4; i++) {
        #pragma unroll
        for (int rh = 0; rh < 2; rh++) {
            const int row = wy*64 + 16*i + g + 8*rh;
            const float inv = 1.f / l[2*i + rh];
            #pragma unroll
            for (int j2 = 0; j2 < 2; j2++) {
                float2 v;
                v.x = accO[i][j2][2*rh  ] * inv;
                v.y = accO[i][j2][2*rh+1] * inv;
                *(float2*)&Yg[base + (long)(qb*128 + row)*DMODEL + wx*16 + 8*j2 + 2*t] = v;
            }
        }
    }
}

// ===========================================================================
// LayerNorm / pos-add
// ===========================================================================
__global__ void add_ln_k(const float* __restrict__ X, const float* __restrict__ Y,
                         const float* __restrict__ g, const float* __restrict__ b,
                         float* __restrict__ O)
{
    const long row = blockIdx.x;
    const float* x = X + row * DMODEL;
    const float* y = Y + row * DMODEL;
    float* o = O + row * DMODEL;
    const int t = threadIdx.x;
    __shared__ float sm[4];

    float v[4];
    float s = 0.f;
    #pragma unroll
    for (int i = 0; i < 4; i++) {
        int j = t + i*128;
        v[i] = x[j] + y[j];
        s += v[i];
    }
    #pragma unroll
    for (int o2 = 16; o2 > 0; o2 >>= 1) s += __shfl_xor_sync(0xffffffffu, s, o2);
    if ((t & 31) == 0) sm[t >> 5] = s;
    __syncthreads();
    const float mu = (sm[0]+sm[1]+sm[2]+sm[3]) * (1.f/DMODEL);
    __syncthreads();
    float var = 0.f;
    #pragma unroll
    for (int i = 0; i < 4; i++) { float d = v[i]-mu; var += d*d; }
    #pragma unroll
    for (int o2 = 16; o2 > 0; o2 >>= 1) var += __shfl_xor_sync(0xffffffffu, var, o2);
    if ((t & 31) == 0) sm[t >> 5] = var;
    __syncthreads();
    const float rs = rsqrtf((sm[0]+sm[1]+sm[2]+sm[3]) * (1.f/DMODEL) + 1e-5f);
    #pragma unroll
    for (int i = 0; i < 4; i++) {
        int j = t + i*128;
        o[j] = (v[i]-mu)*rs*g[j] + b[j];
    }
}

__global__ void addpos_k(const float* __restrict__ x, const float* __restrict__ pos,
                         float* __restrict__ o)
{
    long idx = (long)blockIdx.x * 256 + threadIdx.x;
    long sd  = idx % ((long)SEQ * DMODEL);
    o[idx] = x[idx] + pos[sd];
}

// ===========================================================================
// Host-side launch helpers
// ===========================================================================
static const int SMEM_D = 2*(128*20 + 128*20)*4;   // 40960 B

static void dense32(const float* A, const float* Bt, const float* bias, float* C,
                    int M, int N, int K, long sBb, long sCb, long sbz, int nz)
{
    dim3 grid(N/128, M/128, nz);
    gemm_tf32_k<true><<<grid,256,SMEM_D>>>(A,Bt,bias,C,K, K,K,N, sBb,sCb,sbz);
}
static void dense16(const float* A, const uint32_t* Whi, const uint32_t* Wlo,
                    const float* bias, float* C, int M, int N, int K, int ldw, bool relu)
{
    dim3 grid(N/128, M/128, 1);
    if (relu)
        gemm_bf16_k<true,true ><<<grid,256,SMEM_B16>>>(A,Whi,Wlo,bias,C,K, K,ldw,N);
    else
        gemm_bf16_k<true,false><<<grid,256,SMEM_B16>>>(A,Whi,Wlo,bias,C,K, K,ldw,N);
}

extern "C" void kernel_launch(void* const* d_in, const int* in_sizes, int n_in,
                              void* d_out, int out_size)
{
    const float* kv   = (const float*)d_in[0];
    const float* xin  = (const float*)d_in[1];
    const float* pos  = (const float*)d_in[2];
    const float* sqW  = (const float*)d_in[3];  const float* sqb = (const float*)d_in[4];
    const float* skW  = (const float*)d_in[5];  const float* skb = (const float*)d_in[6];
    const float* svW  = (const float*)d_in[7];  const float* svb = (const float*)d_in[8];
    const float* soW  = (const float*)d_in[9];  const float* sob = (const float*)d_in[10];
    const float* cqW  = (const float*)d_in[11]; const float* cqb = (const float*)d_in[12];
    const float* ckW  = (const float*)d_in[13]; const float* ckb = (const float*)d_in[14];
    const float* cvW  = (const float*)d_in[15]; const float* cvb = (const float*)d_in[16];
    const float* coW  = (const float*)d_in[17]; const float* cob = (const float*)d_in[18];
    const float* f1W  = (const float*)d_in[19]; const float* f1b = (const float*)d_in[20];
    const float* f2W  = (const float*)d_in[21]; const float* f2b = (const float*)d_in[22];
    const float* g1   = (const float*)d_in[23]; const float* b1  = (const float*)d_in[24];
    const float* g2   = (const float*)d_in[25]; const float* b2  = (const float*)d_in[26];
    const float* g3   = (const float*)d_in[27]; const float* b3  = (const float*)d_in[28];
    float* out = (float*)d_out;

    cudaFuncSetAttribute(gemm_tf32_k<true>, cudaFuncAttributeMaxDynamicSharedMemorySize, SMEM_D);
    cudaFuncSetAttribute(gemm_bf16_k<true,false>, cudaFuncAttributeMaxDynamicSharedMemorySize, SMEM_B16);
    cudaFuncSetAttribute(gemm_bf16_k<true,true >, cudaFuncAttributeMaxDynamicSharedMemorySize, SMEM_B16);
    cudaFuncSetAttribute(flash_k<true >, cudaFuncAttributeMaxDynamicSharedMemorySize, FLASH_SMEM);
    cudaFuncSetAttribute(flash_k<false>, cudaFuncAttributeMaxDynamicSharedMemorySize, FLASH_SMEM);

    float *px,*pqkv,*py,*pt,*pf,*pwt,*pbias;
    uint32_t *pwhi,*pwlo;
    cudaGetSymbolAddress((void**)&px, g_x);
    cudaGetSymbolAddress((void**)&pqkv, g_qkv);
    cudaGetSymbolAddress((void**)&py, g_y);
    cudaGetSymbolAddress((void**)&pt, g_t);
    cudaGetSymbolAddress((void**)&pf, g_f);
    cudaGetSymbolAddress((void**)&pwt, g_wt);
    cudaGetSymbolAddress((void**)&pwhi, g_whi);
    cudaGetSymbolAddress((void**)&pwlo, g_wlo);
    cudaGetSymbolAddress((void**)&pbias, g_bias);

    const long DD = (long)DMODEL*DMODEL;
    const long MD = (long)MROWS*DMODEL;

    float* pq = pqkv;
    float* pk = pqkv + MD;
    float* pv = pqkv + 2*MD;

    // tf32 transposed fams in g_wt: sq@0, sk@12DD, cq@24DD, ck@36DD
    float* sqT = pwt;         float* skT = pwt + 12*DD;
    float* cqT = pwt + 24*DD; float* ckT = pwt + 36*DD;

    // bf16 pre-split fams in g_whi/g_wlo (uint32 offsets)
    const long WDD = 131072;   // 512*256 per layer
    const long WF  = 524288;
    const long SV = 0, SO = 12*WDD, CV = 24*WDD, CO = 36*WDD;
    const long F1 = 48*WDD, F2 = F1 + 12*WF;

    {
        dim3 blk(32, 8);
        transpose4_k<<<dim3(16,16,4*NLAYERS), blk>>>(sqW, skW, cqW, ckW, pwt);
        tsplit4_k<<<dim3(16,16,4*NLAYERS), blk>>>(svW, soW, cvW, coW, pwhi, pwlo);
        tsplit_k<<<dim3(64,16,NLAYERS), blk>>>(f1W, pwhi + F1, pwlo + F1, DMODEL, FDIM);
        tsplit_k<<<dim3(16,64,NLAYERS), blk>>>(f2W, pwhi + F2, pwlo + F2, FDIM, DMODEL);
        packbias_k<<<(4*NLAYERS*DMODEL)/256, 256>>>(sqb, skb, sqb, sqb, pbias);
    }

    addpos_k<<<(MROWS*DMODEL)/256, 256>>>(xin, pos, px);

    const long LB = (long)NLAYERS*DMODEL;
    const dim3 fgrid(SEQ/128, BATCH*NHEADS);

    for (int l = 0; l < NLAYERS; l++) {
        // ---- self-attention (causal) ----
        dense32(px, sqT + l*DD, pbias + l*DMODEL, pq,
                MROWS, DMODEL, DMODEL, 12*DD, MD, LB, 2);      // Q and K batched
        dense16(px, pwhi + SV + l*WDD, pwlo + SV + l*WDD, svb + l*DMODEL, pv,
                MROWS, DMODEL, DMODEL, 256, false);
        flash_k<true ><<<fgrid, 256, FLASH_SMEM>>>(pq, pk, pv, py);
        dense16(py, pwhi + SO + l*WDD, pwlo + SO + l*WDD, sob + l*DMODEL, pt,
                MROWS, DMODEL, DMODEL, 256, false);
        add_ln_k<<<MROWS, 128>>>(px, pt, g1 + l*DMODEL, b1 + l*DMODEL, px);

        // ---- cross-attention ----
        dense32(px, cqT + l*DD, cqb + l*DMODEL, pq, MROWS, DMODEL, DMODEL, 0, 0, 0, 1);
        dense32(kv, ckT + l*DD, ckb + l*DMODEL, pk, MROWS, DMODEL, DMODEL, 0, 0, 0, 1);
        dense16(kv, pwhi + CV + l*WDD, pwlo + CV + l*WDD, cvb + l*DMODEL, pv,
                MROWS, DMODEL, DMODEL, 256, false);
        flash_k<false><<<fgrid, 256, FLASH_SMEM>>>(pq, pk, pv, py);
        dense16(py, pwhi + CO + l*WDD, pwlo + CO + l*WDD, cob + l*DMODEL, pt,
                MROWS, DMODEL, DMODEL, 256, false);
        add_ln_k<<<MROWS, 128>>>(px, pt, g2 + l*DMODEL, b2 + l*DMODEL, px);

        // ---- FFN ----
        dense16(px, pwhi + F1 + l*WF, pwlo + F1 + l*WF, f1b + l*FDIM, pf,
                MROWS, FDIM, DMODEL, 256, true);
        dense16(pf, pwhi + F2 + l*WF, pwlo + F2 + l*WF, f2b + l*DMODEL, pt,
                MROWS, DMODEL, FDIM, 1024, false);
        add_ln_k<<<MROWS, 128>>>(px, pt, g3 + l*DMODEL, b3 + l*DMODEL,
                                 (l == NLAYERS-1) ? out : px);
    }
}